// round 9
// baseline (speedup 1.0000x reference)
#include <cuda_runtime.h>
#include <cuda_bf16.h>
#include <cstdint>
#include <math.h>

#define VOCABSZ 32000
#define VPAD    32128
#define WORDVEC 256
#define HIDDEN  512
#define TSTEPS  256
#define NBATCH  16
#define G4      2048
#define MROWS   4096
#define NGRP    4
#define GCOLS   8000
#define VTILES  63
#define LOG2E   1.44269504f

// ---------------- device scratch ----------------
__device__ float          g_xw[TSTEPS * NBATCH * G4];
__device__ float          g_hall[MROWS * HIDDEN];          // [t][n][k] fp32
__device__ __nv_bfloat16  g_hb[MROWS * HIDDEN];            // bf16 copy (written by lstm)
__device__ __nv_bfloat16  g_wvb[(size_t)VPAD * HIDDEN];    // Wv^T bf16 [v][k]
__device__ __nv_bfloat16  g_xb[MROWS * WORDVEC];           // gathered embeddings bf16
__device__ __nv_bfloat16  g_wxT[G4 * WORDVEC];             // Wx^T bf16
__device__ float          g_bv2[VPAD];                     // bv * LOG2E
__device__ float          g_hT2[2][HIDDEN * NBATCH];       // h state double buffer [k][n]
__device__ unsigned       g_flags[TSTEPS * 128];           // flag-array grid barrier
__device__ float          g_ps[NGRP * MROWS];
__device__ float          g_lt[MROWS];

// ---------------- helpers ----------------
__device__ __forceinline__ float sigf(float x) { return __fdividef(1.f, 1.f + __expf(-x)); }
__device__ __forceinline__ float tanhf_fast(float x) { return __fdividef(2.f, 1.f + __expf(-2.f * x)) - 1.f; }
__device__ __forceinline__ uint32_t smem_to_u32(const void* p) {
    uint32_t a;
    asm("{ .reg .u64 t; cvta.to.shared.u64 t, %1; cvt.u32.u64 %0, t; }" : "=r"(a) : "l"(p));
    return a;
}
#define LDSM_X4(r, addr) asm volatile( \
    "ldmatrix.sync.aligned.m8n8.x4.shared.b16 {%0,%1,%2,%3}, [%4];" \
    : "=r"((r)[0]), "=r"((r)[1]), "=r"((r)[2]), "=r"((r)[3]) : "r"(addr))
#define MMA16816(d, a, b0, b1) asm volatile( \
    "mma.sync.aligned.m16n8k16.row.col.f32.bf16.bf16.f32 " \
    "{%0,%1,%2,%3}, {%4,%5,%6,%7}, {%8,%9}, {%0,%1,%2,%3};" \
    : "+f"((d)[0]), "+f"((d)[1]), "+f"((d)[2]), "+f"((d)[3]) \
    : "r"((a)[0]), "r"((a)[1]), "r"((a)[2]), "r"((a)[3]), "r"(b0), "r"(b1))

// packed f32x2 FMA (sm_100+): acc = a*w2 + acc, two fp32 lanes per instruction.
// carried as 64-bit integers for the "l" constraint.
typedef unsigned long long u64;
__device__ __forceinline__ void ffma2(u64& acc, u64 a, u64 w2) {
    asm("fma.rn.f32x2 %0, %1, %2, %0;" : "+l"(acc) : "l"(a), "l"(w2));
}
__device__ __forceinline__ u64 pack2(float w) {
    u64 r;
    asm("mov.b64 %0, {%1, %2};" : "=l"(r) : "r"(__float_as_uint(w)), "r"(__float_as_uint(w)));
    return r;
}

__device__ __forceinline__ float exp2_fast(float t) {
    int i = __float2int_rn(t);
    float f = t - (float)i;
    float p = fmaf(f, 0.00133335581f, 0.00961812911f);
    p = fmaf(f, p, 0.0555041087f);
    p = fmaf(f, p, 0.240226507f);
    p = fmaf(f, p, 0.693147181f);
    p = fmaf(f, p, 1.0f);
    return __int_as_float(__float_as_int(p) + (i << 23));
}

// flag-array grid barrier: block b sets g_flags[t*128+b]; 128 threads poll all flags.
__device__ __forceinline__ void grid_barrier_flags(int t, int bid, int tid) {
    __threadfence();
    __syncthreads();
    if (tid == 0) ((volatile unsigned*)g_flags)[t * 128 + bid] = 1u;
    if (tid < 128) {
        volatile unsigned* f = &((volatile unsigned*)g_flags)[t * 128 + tid];
        while (*f == 0u) { }
    }
    __syncthreads();
    __threadfence();
}

// ---------------- init ----------------
__global__ void __launch_bounds__(256) init_kernel(
    const float* __restrict__ h_init, const float* __restrict__ bv)
{
    int gid = blockIdx.x * 256 + threadIdx.x;            // 8192 threads
    #pragma unroll
    for (int q = 0; q < 4; ++q) g_flags[gid + q * 8192] = 0u;
    if (gid < HIDDEN * NBATCH) g_hT2[0][gid] = h_init[gid >> 4];
    for (int j = gid; j < (VPAD - VOCABSZ) * HIDDEN; j += 8192)
        g_wvb[(size_t)VOCABSZ * HIDDEN + j] = __float2bfloat16(0.f);
    for (int j = gid; j < VPAD; j += 8192)
        g_bv2[j] = (j < VOCABSZ) ? bv[j] * LOG2E : 0.f;
}

// ---------------- Wv transpose + bf16 ----------------
__global__ void __launch_bounds__(256) conv_wv_kernel(const float* __restrict__ Wv) {
    __shared__ float sh[32 * 33];
    int n0 = blockIdx.x * 32, k0 = blockIdx.y * 32;
    int tx = threadIdx.x & 31, ty = threadIdx.x >> 5;
    #pragma unroll
    for (int i = 0; i < 4; ++i) {
        int k = ty + i * 8;
        sh[k * 33 + tx] = Wv[(size_t)(k0 + k) * VOCABSZ + n0 + tx];
    }
    __syncthreads();
    #pragma unroll
    for (int i = 0; i < 4; ++i) {
        int n = ty + i * 8;
        g_wvb[(size_t)(n0 + n) * HIDDEN + k0 + tx] = __float2bfloat16(sh[tx * 33 + n]);
    }
}

// ---------------- Wx transpose + bf16 ----------------
__global__ void __launch_bounds__(256) conv_wx_kernel(const float* __restrict__ Wx) {
    __shared__ float sh[32 * 33];
    int n0 = blockIdx.x * 32, k0 = blockIdx.y * 32;
    int tx = threadIdx.x & 31, ty = threadIdx.x >> 5;
    #pragma unroll
    for (int i = 0; i < 4; ++i) {
        int k = ty + i * 8;
        sh[k * 33 + tx] = Wx[(k0 + k) * G4 + n0 + tx];
    }
    __syncthreads();
    #pragma unroll
    for (int i = 0; i < 4; ++i) {
        int n = ty + i * 8;
        g_wxT[(n0 + n) * WORDVEC + k0 + tx] = __float2bfloat16(sh[tx * 33 + n]);
    }
}

// ---------------- gather embeddings -> bf16 ----------------
__global__ void __launch_bounds__(256) gather_x_kernel(
    const int* __restrict__ captions, const float* __restrict__ W_embed)
{
    int gid = blockIdx.x * 256 + threadIdx.x;
    int idx = gid * 4;
    int r = idx >> 8, d = idx & 255;
    int tok = captions[(r & 15) * 257 + (r >> 4)];
    float4 v = *(const float4*)&W_embed[tok * WORDVEC + d];
    __nv_bfloat16 o[4];
    o[0] = __float2bfloat16(v.x); o[1] = __float2bfloat16(v.y);
    o[2] = __float2bfloat16(v.z); o[3] = __float2bfloat16(v.w);
    *(uint2*)&g_xb[idx] = *(const uint2*)o;
}

// ---------------- embed GEMM (bf16 mma.sync) ----------------
#define E_A_STRIDE 264
#define E_B_OFF    67584
#define E_SMEM     135168
extern __shared__ __align__(16) char dsm_e[];
__global__ void __launch_bounds__(256, 1) embed_mma_kernel(const float* __restrict__ b) {
    __nv_bfloat16* As = (__nv_bfloat16*)dsm_e;
    __nv_bfloat16* Bs = (__nv_bfloat16*)(dsm_e + E_B_OFF);
    const int tid = threadIdx.x, lane = tid & 31, wid = tid >> 5;
    const int wm = wid >> 1, wn = wid & 1;
    const int mblk = blockIdx.x >> 4, nblk = blockIdx.x & 15;

    const uint4* asrc = (const uint4*)(g_xb + mblk * 128 * WORDVEC);
    const uint4* bsrc = (const uint4*)(g_wxT + nblk * 128 * WORDVEC);
    #pragma unroll
    for (int q = 0; q < 16; ++q) {
        int i = q * 256 + tid;
        int r = i >> 5, u = i & 31;
        *(uint4*)(As + r * E_A_STRIDE + u * 8) = asrc[i];
        *(uint4*)(Bs + r * E_A_STRIDE + u * 8) = bsrc[i];
    }
    __syncthreads();

    const uint32_t a_base = smem_to_u32(As);
    const uint32_t a_lane = (uint32_t)((lane & 15) * E_A_STRIDE + (lane >> 4) * 8) * 2;
    const int bq = lane >> 3;
    const uint32_t b_lane = (uint32_t)(((bq >> 1) * 8 + (lane & 7)) * E_A_STRIDE + (bq & 1) * 8) * 2;
    const uint32_t b_base = smem_to_u32(Bs) + (uint32_t)(wn * 64 * E_A_STRIDE) * 2;

    float d[2][8][4];
    #pragma unroll
    for (int mt = 0; mt < 2; ++mt)
        #pragma unroll
        for (int nt = 0; nt < 8; ++nt)
            #pragma unroll
            for (int e = 0; e < 4; ++e) d[mt][nt][e] = 0.f;

    #pragma unroll
    for (int k16 = 0; k16 < 16; ++k16) {
        const uint32_t koff = (uint32_t)(k16 * 16) * 2;
        uint32_t a[2][4];
        #pragma unroll
        for (int mt = 0; mt < 2; ++mt) {
            LDSM_X4(a[mt], a_base + a_lane + (uint32_t)((wm * 32 + mt * 16) * E_A_STRIDE) * 2 + koff);
        }
        #pragma unroll
        for (int np = 0; np < 4; ++np) {
            uint32_t bb[4];
            LDSM_X4(bb, b_base + b_lane + (uint32_t)(np * 16 * E_A_STRIDE) * 2 + koff);
            MMA16816(d[0][np * 2 + 0], a[0], bb[0], bb[1]);
            MMA16816(d[0][np * 2 + 1], a[0], bb[2], bb[3]);
            MMA16816(d[1][np * 2 + 0], a[1], bb[0], bb[1]);
            MMA16816(d[1][np * 2 + 1], a[1], bb[2], bb[3]);
        }
    }

    const int cbase = nblk * 128 + wn * 64 + (lane & 3) * 2;
    #pragma unroll
    for (int mt = 0; mt < 2; ++mt)
        #pragma unroll
        for (int rh = 0; rh < 2; ++rh) {
            int row = mblk * 128 + wm * 32 + mt * 16 + rh * 8 + (lane >> 2);
            #pragma unroll
            for (int nt = 0; nt < 8; ++nt) {
                int c = cbase + nt * 8;
                float2 v;
                v.x = d[mt][nt][rh * 2 + 0] + b[c];
                v.y = d[mt][nt][rh * 2 + 1] + b[c + 1];
                *(float2*)&g_xw[(size_t)row * G4 + c] = v;
            }
        }
}

// ---------------- persistent LSTM: f32x2 packed FMA + flag barrier ----------------
extern __shared__ float dsm_l[];
__global__ void __launch_bounds__(256) lstm_kernel(const float* __restrict__ Wh) {
    float* Whs  = dsm_l;           // [512][16]
    float* h_sh = dsm_l + 8192;    // [512][16]
    float* part = dsm_l + 16384;   // [256][16]
    float* a_sh = dsm_l + 20480;   // [256]
    float* c_sh = dsm_l + 20736;   // [64]

    const int bid = blockIdx.x, tid = threadIdx.x;
    const int h0 = bid * 4;
    const int kc = tid >> 4, j16 = tid & 15;

    for (int i = tid; i < 8192; i += 256) {
        int k = i >> 4, j = i & 15;
        int jcol = (j >> 2) * 512 + h0 + (j & 3);
        Whs[i] = Wh[k * G4 + jcol];
    }
    if (tid < 64) c_sh[tid] = 0.f;

    const int gn = tid >> 2, ghq = tid & 3;
    const int ghcol = h0 + ghq;

    for (int t = 0; t < TSTEPS; ++t) {
        float4* h4 = (float4*)h_sh;
        const float4* src4 = (const float4*)g_hT2[t & 1];
        #pragma unroll
        for (int i = 0; i < 8; ++i) h4[tid + i * 256] = __ldcg(&src4[tid + i * 256]);

        float xwv[4];
        if (tid < 64) {
            #pragma unroll
            for (int g = 0; g < 4; ++g)
                xwv[g] = g_xw[(size_t)(t * NBATCH + gn) * G4 + g * 512 + ghcol];
        }
        __syncthreads();

        // packed f32x2 accumulation: acc2[q] = (acc[2q], acc[2q+1])
        u64 acc2[8];
        #pragma unroll
        for (int q = 0; q < 8; ++q) acc2[q] = 0ull;
        const u64* hp2 = (const u64*)((const float4*)h_sh + kc * 128);
        #pragma unroll 2
        for (int kk = 0; kk < 32; ++kk) {
            u64 w2 = pack2(Whs[(kc * 32 + kk) * 16 + j16]);
            #pragma unroll
            for (int q = 0; q < 8; ++q) ffma2(acc2[q], hp2[kk * 8 + q], w2);
        }
        u64* pp = (u64*)(part + tid * 16);
        #pragma unroll
        for (int q = 0; q < 8; ++q) pp[q] = acc2[q];
        __syncthreads();

        float ssum = 0.f;
        #pragma unroll
        for (int q = 0; q < 16; ++q) ssum += part[q * 256 + tid];
        a_sh[tid] = ssum;
        __syncthreads();

        if (tid < 64) {
            float av0 = a_sh[(0 * 4 + ghq) * 16 + gn] + xwv[0];
            float av1 = a_sh[(1 * 4 + ghq) * 16 + gn] + xwv[1];
            float av2 = a_sh[(2 * 4 + ghq) * 16 + gn] + xwv[2];
            float av3 = a_sh[(3 * 4 + ghq) * 16 + gn] + xwv[3];
            float ig = sigf(av0), fg = sigf(av1), og = sigf(av2), gg = tanhf_fast(av3);
            float c  = fg * c_sh[tid] + ig * gg;
            float hh = og * tanhf_fast(c);
            c_sh[tid] = c;
            g_hT2[(t & 1) ^ 1][ghcol * 16 + gn] = hh;
            g_hall[t * (NBATCH * HIDDEN) + gn * HIDDEN + ghcol] = hh;
            g_hb[t * (NBATCH * HIDDEN) + gn * HIDDEN + ghcol] = __float2bfloat16(hh);
        }
        grid_barrier_flags(t, bid, tid);
    }
}

// ---------------- target logits ----------------
__global__ void __launch_bounds__(256) tgt_kernel(
    const int* __restrict__ captions, const float* __restrict__ bv)
{
    int wid = threadIdx.x >> 5, lane = threadIdx.x & 31;
    int r = blockIdx.x * 8 + wid;
    int tg = captions[(r & 15) * 257 + (r >> 4) + 1];
    const float* hr = &g_hall[r * HIDDEN];
    const __nv_bfloat16* wv = &g_wvb[(size_t)tg * HIDDEN];
    float s = 0.f;
    #pragma unroll
    for (int i = 0; i < 16; ++i) {
        int k = lane + i * 32;
        s = fmaf(hr[k], __bfloat162float(wv[k]), s);
    }
    #pragma unroll
    for (int o = 16; o > 0; o >>= 1) s += __shfl_xor_sync(0xffffffffu, s, o);
    if (lane == 0) g_lt[r] = s + bv[tg];
}

// ---------------- vocab: bf16 mma.sync + streaming exp-sum ----------------
#define V_A_STRIDE 520
#define V_B_OFF    133120
#define V_B_SZ     18432
#define V_B_STRIDE 72
#define V_RED_OFF  169984
#define V_SMEM     171008
extern __shared__ __align__(16) char dsm_v[];
__global__ void __launch_bounds__(256, 1) vocab_kernel() {
    __nv_bfloat16* As = (__nv_bfloat16*)dsm_v;
    const int tid = threadIdx.x, lane = tid & 31, wid = tid >> 5;
    const int wm = wid >> 1, wn = wid & 1;
    const int mblk = blockIdx.x >> 2, g = blockIdx.x & 3;
    const int gbase = g * GCOLS;

    {
        const uint4* src = (const uint4*)(g_hb + (size_t)(mblk * 128) * HIDDEN);
        for (int i = tid; i < 8192; i += 256) {
            int r = i >> 6, u = i & 63;
            *(uint4*)(As + r * V_A_STRIDE + u * 8) = src[i];
        }
    }
    __syncthreads();

    const uint32_t a_base = smem_to_u32(dsm_v);
    const uint32_t a_lane = (uint32_t)((lane & 15) * V_A_STRIDE + (lane >> 4) * 8) * 2;
    const int bq = lane >> 3;
    const uint32_t b_lane = (uint32_t)(((bq >> 1) * 8 + (lane & 7)) * V_B_STRIDE + (bq & 1) * 8) * 2;

    float rs[2][2] = {{0.f, 0.f}, {0.f, 0.f}};

    for (int tt = 0; tt < VTILES; ++tt) {
        const int nbase = gbase + tt * 128;
        float bb[16];
        {
            int cb = nbase + wn * 64 + (lane & 3) * 2;
            #pragma unroll
            for (int nt = 0; nt < 8; ++nt) {
                bb[nt * 2 + 0] = g_bv2[cb + nt * 8 + 0];
                bb[nt * 2 + 1] = g_bv2[cb + nt * 8 + 1];
            }
        }
        float d[2][8][4];
        #pragma unroll
        for (int mt = 0; mt < 2; ++mt)
            #pragma unroll
            for (int nt = 0; nt < 8; ++nt)
                #pragma unroll
                for (int e = 0; e < 4; ++e) d[mt][nt][e] = 0.f;

        uint4 ld[4];
        #pragma unroll
        for (int q = 0; q < 4; ++q) {
            int j = q * 256 + tid;
            int n = j >> 3, u = j & 7;
            ld[q] = *(const uint4*)(g_wvb + (size_t)(nbase + n) * HIDDEN + u * 8);
        }
        #pragma unroll
        for (int q = 0; q < 4; ++q) {
            int j = q * 256 + tid;
            int n = j >> 3, u = j & 7;
            *(uint4*)((__nv_bfloat16*)(dsm_v + V_B_OFF) + n * V_B_STRIDE + u * 8) = ld[q];
        }
        __syncthreads();

        for (int kc = 0; kc < 8; ++kc) {
            if (kc < 7) {
                #pragma unroll
                for (int q = 0; q < 4; ++q) {
                    int j = q * 256 + tid;
                    int n = j >> 3, u = j & 7;
                    ld[q] = *(const uint4*)(g_wvb + (size_t)(nbase + n) * HIDDEN + (kc + 1) * 64 + u * 8);
                }
            }
            const uint32_t b_base = smem_to_u32(dsm_v + V_B_OFF + (kc & 1) * V_B_SZ) + (uint32_t)(wn * 64 * V_B_STRIDE) * 2;
            #pragma unroll
            for (int k16 = 0; k16 < 4; ++k16) {
                uint32_t a[2][4];
                #pragma unroll
                for (int mt = 0; mt < 2; ++mt) {
                    uint32_t aaddr = a_base + a_lane +
                        (uint32_t)((wm * 32 + mt * 16) * V_A_STRIDE + kc * 64 + k16 * 16) * 2;
                    LDSM_X4(a[mt], aaddr);
                }
                #pragma unroll
                for (int np = 0; np < 4; ++np) {
                    uint32_t b[4];
                    uint32_t baddr = b_base + b_lane + (uint32_t)(np * 16 * V_B_STRIDE + k16 * 16) * 2;
                    LDSM_X4(b, baddr);
                    MMA16816(d[0][np * 2 + 0], a[0], b[0], b[1]);
                    MMA16816(d[0][np * 2 + 1], a[0], b[2], b[3]);
                    MMA16816(d[1][np * 2 + 0], a[1], b[0], b[1]);
                    MMA16816(d[1][np * 2 + 1], a[1], b[2], b[3]);
                }
            }
            if (kc < 7) {
                __nv_bfloat16* dst = (__nv_bfloat16*)(dsm_v + V_B_OFF + ((kc + 1) & 1) * V_B_SZ);
                #pragma unroll
                for (int q = 0; q < 4; ++q) {
                    int j = q * 256 + tid;
                    int n = j >> 3, u = j & 7;
                    *(uint4*)(dst + n * V_B_STRIDE + u * 8) = ld[q];
                }
            }
            __syncthreads();
        }

        if (!(tt == VTILES - 1 && wn == 1)) {
            #pragma unroll
            for (int mt = 0; mt < 2; ++mt)
                #pragma unroll
                for (int rh = 0; rh < 2; ++rh) {
                    float s = 0.f;
                    #pragma unroll
                    for (int nt = 0; nt < 8; ++nt) {
                        s += exp2_fast(fmaf(d[mt][nt][rh * 2 + 0], LOG2E, bb[nt * 2 + 0]));
                        s += exp2_fast(fmaf(d[mt][nt][rh * 2 + 1], LOG2E, bb[nt * 2 + 1]));
                    }
                    rs[mt][rh] += s;
                }
        }
    }

    float* red = (float*)(dsm_v + V_RED_OFF);
    #pragma unroll
    for (int mt = 0; mt < 2; ++mt)
        #pragma unroll
        for (int rh = 0; rh < 2; ++rh) {
            float v = rs[mt][rh];
            v += __shfl_xor_sync(0xffffffffu, v, 1);
            v += __shfl_xor_sync(0xffffffffu, v, 2);
            if ((lane & 3) == 0) {
                int row = wm * 32 + mt * 16 + rh * 8 + (lane >> 2);
                red[row * 2 + wn] = v;
            }
        }
    __syncthreads();
    if (tid < 128) {
        g_ps[g * MROWS + mblk * 128 + tid] = red[tid * 2 + 0] + red[tid * 2 + 1];
    }
}

// ---------------- combine ----------------
__global__ void __launch_bounds__(1024) combine_kernel(
    const int* __restrict__ captions, float* __restrict__ out)
{
    __shared__ float sh[1024];
    int tid = threadIdx.x;
    float local = 0.f;
    for (int r = tid; r < MROWS; r += 1024) {
        float S = g_ps[r] + g_ps[MROWS + r] + g_ps[2 * MROWS + r] + g_ps[3 * MROWS + r];
        int tg = captions[(r & 15) * 257 + (r >> 4) + 1];
        if (tg != 0) local += logf(S) - g_lt[r];
    }
    sh[tid] = local;
    __syncthreads();
    for (int o = 512; o > 0; o >>= 1) {
        if (tid < o) sh[tid] += sh[tid + o];
        __syncthreads();
    }
    if (tid == 0) out[0] = sh[0] * (1.f / NBATCH);
}

// ---------------- launch ----------------
extern "C" void kernel_launch(void* const* d_in, const int* in_sizes, int n_in,
                              void* d_out, int out_size) {
    const int*   captions = (const int*)d_in[0];
    const float* W_embed  = (const float*)d_in[1];
    const float* Wx       = (const float*)d_in[2];
    const float* Wh       = (const float*)d_in[3];
    const float* b        = (const float*)d_in[4];
    const float* W_vocab  = (const float*)d_in[5];
    const float* b_vocab  = (const float*)d_in[6];
    const float* h_init   = (const float*)d_in[7];

    cudaFuncSetAttribute(lstm_kernel,      cudaFuncAttributeMaxDynamicSharedMemorySize, 83200);
    cudaFuncSetAttribute(vocab_kernel,     cudaFuncAttributeMaxDynamicSharedMemorySize, V_SMEM);
    cudaFuncSetAttribute(embed_mma_kernel, cudaFuncAttributeMaxDynamicSharedMemorySize, E_SMEM);

    init_kernel<<<32, 256>>>(h_init, b_vocab);
    gather_x_kernel<<<256, 256>>>(captions, W_embed);
    conv_wx_kernel<<<dim3(G4 / 32, WORDVEC / 32), 256>>>(Wx);
    conv_wv_kernel<<<dim3(VOCABSZ / 32, HIDDEN / 32), 256>>>(W_vocab);
    embed_mma_kernel<<<512, 256, E_SMEM>>>(b);
    lstm_kernel<<<128, 256, 83200>>>(Wh);
    tgt_kernel<<<512, 256>>>(captions, b_vocab);
    vocab_kernel<<<128, 256, V_SMEM>>>();
    combine_kernel<<<1, 1024>>>(captions, (float*)d_out);
}

// round 10
// speedup vs baseline: 1.9147x; 1.9147x over previous
#include <cuda_runtime.h>
#include <cuda_bf16.h>
#include <cstdint>
#include <math.h>

#define VOCABSZ 32000
#define VPAD    32128
#define WORDVEC 256
#define HIDDEN  512
#define TSTEPS  256
#define NBATCH  16
#define G4      2048
#define MROWS   4096
#define NGRP    4
#define GCOLS   8000
#define VTILES  63
#define LOG2E   1.44269504f

// ---------------- device scratch ----------------
__device__ float          g_xw[TSTEPS * NBATCH * G4];
__device__ float          g_hall[MROWS * HIDDEN];          // [t][n][k] fp32
__device__ __nv_bfloat16  g_hb[MROWS * HIDDEN];            // bf16 copy (written by lstm)
__device__ __nv_bfloat16  g_wvb[(size_t)VPAD * HIDDEN];    // Wv^T bf16 [v][k]
__device__ __nv_bfloat16  g_xb[MROWS * WORDVEC];           // gathered embeddings bf16
__device__ __nv_bfloat16  g_wxT[G4 * WORDVEC];             // Wx^T bf16
__device__ float          g_bv2[VPAD];                     // bv * LOG2E
__device__ float          g_hT2[2][HIDDEN * NBATCH];       // h state double buffer [k][n]
__device__ unsigned       g_barc[TSTEPS * 8];              // 8-way split barrier counters
__device__ float          g_ps[NGRP * MROWS];
__device__ float          g_lt[MROWS];

// ---------------- helpers ----------------
__device__ __forceinline__ float sigf(float x) { return __fdividef(1.f, 1.f + __expf(-x)); }
__device__ __forceinline__ float tanhf_fast(float x) { return __fdividef(2.f, 1.f + __expf(-2.f * x)) - 1.f; }
__device__ __forceinline__ uint32_t smem_to_u32(const void* p) {
    uint32_t a;
    asm("{ .reg .u64 t; cvta.to.shared.u64 t, %1; cvt.u32.u64 %0, t; }" : "=r"(a) : "l"(p));
    return a;
}
#define LDSM_X4(r, addr) asm volatile( \
    "ldmatrix.sync.aligned.m8n8.x4.shared.b16 {%0,%1,%2,%3}, [%4];" \
    : "=r"((r)[0]), "=r"((r)[1]), "=r"((r)[2]), "=r"((r)[3]) : "r"(addr))
#define MMA16816(d, a, b0, b1) asm volatile( \
    "mma.sync.aligned.m16n8k16.row.col.f32.bf16.bf16.f32 " \
    "{%0,%1,%2,%3}, {%4,%5,%6,%7}, {%8,%9}, {%0,%1,%2,%3};" \
    : "+f"((d)[0]), "+f"((d)[1]), "+f"((d)[2]), "+f"((d)[3]) \
    : "r"((a)[0]), "r"((a)[1]), "r"((a)[2]), "r"((a)[3]), "r"(b0), "r"(b1))

__device__ __forceinline__ float exp2_fast(float t) {
    int i = __float2int_rn(t);
    float f = t - (float)i;
    float p = fmaf(f, 0.00133335581f, 0.00961812911f);
    p = fmaf(f, p, 0.0555041087f);
    p = fmaf(f, p, 0.240226507f);
    p = fmaf(f, p, 0.693147181f);
    p = fmaf(f, p, 1.0f);
    return __int_as_float(__float_as_int(p) + (i << 23));
}

// 8-way split grid barrier: block b arrives at counter (b&7); 8 threads poll
// their counter until it reaches 16 (128 blocks / 8 counters).
__device__ __forceinline__ void grid_barrier8(int t, int bid, int tid) {
    __threadfence();
    __syncthreads();
    if (tid == 0) atomicAdd(&g_barc[t * 8 + (bid & 7)], 1u);
    if (tid < 8) {
        volatile unsigned* p = &((volatile unsigned*)g_barc)[t * 8 + tid];
        while (*p < 16u) { }
    }
    __syncthreads();
    __threadfence();
}

// ---------------- init ----------------
__global__ void __launch_bounds__(256) init_kernel(
    const float* __restrict__ h_init, const float* __restrict__ bv)
{
    int gid = blockIdx.x * 256 + threadIdx.x;            // 8192 threads
    if (gid < TSTEPS * 8) g_barc[gid] = 0u;
    if (gid < HIDDEN * NBATCH) g_hT2[0][gid] = h_init[gid >> 4];
    for (int j = gid; j < (VPAD - VOCABSZ) * HIDDEN; j += 8192)
        g_wvb[(size_t)VOCABSZ * HIDDEN + j] = __float2bfloat16(0.f);
    for (int j = gid; j < VPAD; j += 8192)
        g_bv2[j] = (j < VOCABSZ) ? bv[j] * LOG2E : 0.f;
}

// ---------------- Wv transpose + bf16 ----------------
__global__ void __launch_bounds__(256) conv_wv_kernel(const float* __restrict__ Wv) {
    __shared__ float sh[32 * 33];
    int n0 = blockIdx.x * 32, k0 = blockIdx.y * 32;
    int tx = threadIdx.x & 31, ty = threadIdx.x >> 5;
    #pragma unroll
    for (int i = 0; i < 4; ++i) {
        int k = ty + i * 8;
        sh[k * 33 + tx] = Wv[(size_t)(k0 + k) * VOCABSZ + n0 + tx];
    }
    __syncthreads();
    #pragma unroll
    for (int i = 0; i < 4; ++i) {
        int n = ty + i * 8;
        g_wvb[(size_t)(n0 + n) * HIDDEN + k0 + tx] = __float2bfloat16(sh[tx * 33 + n]);
    }
}

// ---------------- Wx transpose + bf16 ----------------
__global__ void __launch_bounds__(256) conv_wx_kernel(const float* __restrict__ Wx) {
    __shared__ float sh[32 * 33];
    int n0 = blockIdx.x * 32, k0 = blockIdx.y * 32;
    int tx = threadIdx.x & 31, ty = threadIdx.x >> 5;
    #pragma unroll
    for (int i = 0; i < 4; ++i) {
        int k = ty + i * 8;
        sh[k * 33 + tx] = Wx[(k0 + k) * G4 + n0 + tx];
    }
    __syncthreads();
    #pragma unroll
    for (int i = 0; i < 4; ++i) {
        int n = ty + i * 8;
        g_wxT[(n0 + n) * WORDVEC + k0 + tx] = __float2bfloat16(sh[tx * 33 + n]);
    }
}

// ---------------- gather embeddings -> bf16 ----------------
__global__ void __launch_bounds__(256) gather_x_kernel(
    const int* __restrict__ captions, const float* __restrict__ W_embed)
{
    int gid = blockIdx.x * 256 + threadIdx.x;
    int idx = gid * 4;
    int r = idx >> 8, d = idx & 255;
    int tok = captions[(r & 15) * 257 + (r >> 4)];
    float4 v = *(const float4*)&W_embed[tok * WORDVEC + d];
    __nv_bfloat16 o[4];
    o[0] = __float2bfloat16(v.x); o[1] = __float2bfloat16(v.y);
    o[2] = __float2bfloat16(v.z); o[3] = __float2bfloat16(v.w);
    *(uint2*)&g_xb[idx] = *(const uint2*)o;
}

// ---------------- embed GEMM (bf16 mma.sync) ----------------
#define E_A_STRIDE 264
#define E_B_OFF    67584
#define E_SMEM     135168
extern __shared__ __align__(16) char dsm_e[];
__global__ void __launch_bounds__(256, 1) embed_mma_kernel(const float* __restrict__ b) {
    __nv_bfloat16* As = (__nv_bfloat16*)dsm_e;
    __nv_bfloat16* Bs = (__nv_bfloat16*)(dsm_e + E_B_OFF);
    const int tid = threadIdx.x, lane = tid & 31, wid = tid >> 5;
    const int wm = wid >> 1, wn = wid & 1;
    const int mblk = blockIdx.x >> 4, nblk = blockIdx.x & 15;

    const uint4* asrc = (const uint4*)(g_xb + mblk * 128 * WORDVEC);
    const uint4* bsrc = (const uint4*)(g_wxT + nblk * 128 * WORDVEC);
    #pragma unroll
    for (int q = 0; q < 16; ++q) {
        int i = q * 256 + tid;
        int r = i >> 5, u = i & 31;
        *(uint4*)(As + r * E_A_STRIDE + u * 8) = asrc[i];
        *(uint4*)(Bs + r * E_A_STRIDE + u * 8) = bsrc[i];
    }
    __syncthreads();

    const uint32_t a_base = smem_to_u32(As);
    const uint32_t a_lane = (uint32_t)((lane & 15) * E_A_STRIDE + (lane >> 4) * 8) * 2;
    const int bq = lane >> 3;
    const uint32_t b_lane = (uint32_t)(((bq >> 1) * 8 + (lane & 7)) * E_A_STRIDE + (bq & 1) * 8) * 2;
    const uint32_t b_base = smem_to_u32(Bs) + (uint32_t)(wn * 64 * E_A_STRIDE) * 2;

    float d[2][8][4];
    #pragma unroll
    for (int mt = 0; mt < 2; ++mt)
        #pragma unroll
        for (int nt = 0; nt < 8; ++nt)
            #pragma unroll
            for (int e = 0; e < 4; ++e) d[mt][nt][e] = 0.f;

    #pragma unroll
    for (int k16 = 0; k16 < 16; ++k16) {
        const uint32_t koff = (uint32_t)(k16 * 16) * 2;
        uint32_t a[2][4];
        #pragma unroll
        for (int mt = 0; mt < 2; ++mt) {
            LDSM_X4(a[mt], a_base + a_lane + (uint32_t)((wm * 32 + mt * 16) * E_A_STRIDE) * 2 + koff);
        }
        #pragma unroll
        for (int np = 0; np < 4; ++np) {
            uint32_t bb[4];
            LDSM_X4(bb, b_base + b_lane + (uint32_t)(np * 16 * E_A_STRIDE) * 2 + koff);
            MMA16816(d[0][np * 2 + 0], a[0], bb[0], bb[1]);
            MMA16816(d[0][np * 2 + 1], a[0], bb[2], bb[3]);
            MMA16816(d[1][np * 2 + 0], a[1], bb[0], bb[1]);
            MMA16816(d[1][np * 2 + 1], a[1], bb[2], bb[3]);
        }
    }

    const int cbase = nblk * 128 + wn * 64 + (lane & 3) * 2;
    #pragma unroll
    for (int mt = 0; mt < 2; ++mt)
        #pragma unroll
        for (int rh = 0; rh < 2; ++rh) {
            int row = mblk * 128 + wm * 32 + mt * 16 + rh * 8 + (lane >> 2);
            #pragma unroll
            for (int nt = 0; nt < 8; ++nt) {
                int c = cbase + nt * 8;
                float2 v;
                v.x = d[mt][nt][rh * 2 + 0] + b[c];
                v.y = d[mt][nt][rh * 2 + 1] + b[c + 1];
                *(float2*)&g_xw[(size_t)row * G4 + c] = v;
            }
        }
}

// ---------------- persistent LSTM: 128 blocks, double-buffered h, 1 barrier/step --------
extern __shared__ float dsm_l[];
__global__ void __launch_bounds__(256) lstm_kernel(const float* __restrict__ Wh) {
    float* Whs  = dsm_l;           // [512][16]
    float* h_sh = dsm_l + 8192;    // [512][16]
    float* part = dsm_l + 16384;   // [256][16]
    float* a_sh = dsm_l + 20480;   // [256]
    float* c_sh = dsm_l + 20736;   // [64]

    const int bid = blockIdx.x, tid = threadIdx.x;
    const int h0 = bid * 4;
    const int kc = tid >> 4, j16 = tid & 15;

    for (int i = tid; i < 8192; i += 256) {
        int k = i >> 4, j = i & 15;
        int jcol = (j >> 2) * 512 + h0 + (j & 3);
        Whs[i] = Wh[k * G4 + jcol];
    }
    if (tid < 64) c_sh[tid] = 0.f;

    const int gn = tid >> 2, ghq = tid & 3;
    const int ghcol = h0 + ghq;

    for (int t = 0; t < TSTEPS; ++t) {
        float4* h4 = (float4*)h_sh;
        const float4* src4 = (const float4*)g_hT2[t & 1];
        #pragma unroll
        for (int i = 0; i < 8; ++i) h4[tid + i * 256] = __ldcg(&src4[tid + i * 256]);

        float xwv[4];
        if (tid < 64) {
            #pragma unroll
            for (int g = 0; g < 4; ++g)
                xwv[g] = g_xw[(size_t)(t * NBATCH + gn) * G4 + g * 512 + ghcol];
        }
        __syncthreads();

        float acc[16];
        #pragma unroll
        for (int n = 0; n < 16; ++n) acc[n] = 0.f;
        const float4* hp = (const float4*)h_sh + kc * 128;
        #pragma unroll 2
        for (int kk = 0; kk < 32; ++kk) {
            float w = Whs[(kc * 32 + kk) * 16 + j16];
            float4 a0 = hp[kk * 4 + 0], a1 = hp[kk * 4 + 1], a2 = hp[kk * 4 + 2], a3 = hp[kk * 4 + 3];
            acc[0]=fmaf(a0.x,w,acc[0]);  acc[1]=fmaf(a0.y,w,acc[1]);  acc[2]=fmaf(a0.z,w,acc[2]);  acc[3]=fmaf(a0.w,w,acc[3]);
            acc[4]=fmaf(a1.x,w,acc[4]);  acc[5]=fmaf(a1.y,w,acc[5]);  acc[6]=fmaf(a1.z,w,acc[6]);  acc[7]=fmaf(a1.w,w,acc[7]);
            acc[8]=fmaf(a2.x,w,acc[8]);  acc[9]=fmaf(a2.y,w,acc[9]);  acc[10]=fmaf(a2.z,w,acc[10]); acc[11]=fmaf(a2.w,w,acc[11]);
            acc[12]=fmaf(a3.x,w,acc[12]); acc[13]=fmaf(a3.y,w,acc[13]); acc[14]=fmaf(a3.z,w,acc[14]); acc[15]=fmaf(a3.w,w,acc[15]);
        }
        float4* pp = (float4*)(part + tid * 16);
        pp[0] = make_float4(acc[0], acc[1], acc[2], acc[3]);
        pp[1] = make_float4(acc[4], acc[5], acc[6], acc[7]);
        pp[2] = make_float4(acc[8], acc[9], acc[10], acc[11]);
        pp[3] = make_float4(acc[12], acc[13], acc[14], acc[15]);
        __syncthreads();

        float ssum = 0.f;
        #pragma unroll
        for (int q = 0; q < 16; ++q) ssum += part[q * 256 + tid];
        a_sh[tid] = ssum;
        __syncthreads();

        if (tid < 64) {
            float av0 = a_sh[(0 * 4 + ghq) * 16 + gn] + xwv[0];
            float av1 = a_sh[(1 * 4 + ghq) * 16 + gn] + xwv[1];
            float av2 = a_sh[(2 * 4 + ghq) * 16 + gn] + xwv[2];
            float av3 = a_sh[(3 * 4 + ghq) * 16 + gn] + xwv[3];
            float ig = sigf(av0), fg = sigf(av1), og = sigf(av2), gg = tanhf_fast(av3);
            float c  = fg * c_sh[tid] + ig * gg;
            float hh = og * tanhf_fast(c);
            c_sh[tid] = c;
            g_hT2[(t & 1) ^ 1][ghcol * 16 + gn] = hh;
            g_hall[t * (NBATCH * HIDDEN) + gn * HIDDEN + ghcol] = hh;
            g_hb[t * (NBATCH * HIDDEN) + gn * HIDDEN + ghcol] = __float2bfloat16(hh);
        }
        grid_barrier8(t, bid, tid);
    }
}

// ---------------- target logits ----------------
__global__ void __launch_bounds__(256) tgt_kernel(
    const int* __restrict__ captions, const float* __restrict__ bv)
{
    int wid = threadIdx.x >> 5, lane = threadIdx.x & 31;
    int r = blockIdx.x * 8 + wid;
    int tg = captions[(r & 15) * 257 + (r >> 4) + 1];
    const float* hr = &g_hall[r * HIDDEN];
    const __nv_bfloat16* wv = &g_wvb[(size_t)tg * HIDDEN];
    float s = 0.f;
    #pragma unroll
    for (int i = 0; i < 16; ++i) {
        int k = lane + i * 32;
        s = fmaf(hr[k], __bfloat162float(wv[k]), s);
    }
    #pragma unroll
    for (int o = 16; o > 0; o >>= 1) s += __shfl_xor_sync(0xffffffffu, s, o);
    if (lane == 0) g_lt[r] = s + bv[tg];
}

// ---------------- vocab: bf16 mma.sync + streaming exp-sum ----------------
#define V_A_STRIDE 520
#define V_B_OFF    133120
#define V_B_SZ     18432
#define V_B_STRIDE 72
#define V_RED_OFF  169984
#define V_SMEM     171008
extern __shared__ __align__(16) char dsm_v[];
__global__ void __launch_bounds__(256, 1) vocab_kernel() {
    __nv_bfloat16* As = (__nv_bfloat16*)dsm_v;
    const int tid = threadIdx.x, lane = tid & 31, wid = tid >> 5;
    const int wm = wid >> 1, wn = wid & 1;
    const int mblk = blockIdx.x >> 2, g = blockIdx.x & 3;
    const int gbase = g * GCOLS;

    {
        const uint4* src = (const uint4*)(g_hb + (size_t)(mblk * 128) * HIDDEN);
        for (int i = tid; i < 8192; i += 256) {
            int r = i >> 6, u = i & 63;
            *(uint4*)(As + r * V_A_STRIDE + u * 8) = src[i];
        }
    }
    __syncthreads();

    const uint32_t a_base = smem_to_u32(dsm_v);
    const uint32_t a_lane = (uint32_t)((lane & 15) * V_A_STRIDE + (lane >> 4) * 8) * 2;
    const int bq = lane >> 3;
    const uint32_t b_lane = (uint32_t)(((bq >> 1) * 8 + (lane & 7)) * V_B_STRIDE + (bq & 1) * 8) * 2;

    float rs[2][2] = {{0.f, 0.f}, {0.f, 0.f}};

    for (int tt = 0; tt < VTILES; ++tt) {
        const int nbase = gbase + tt * 128;
        float bb[16];
        {
            int cb = nbase + wn * 64 + (lane & 3) * 2;
            #pragma unroll
            for (int nt = 0; nt < 8; ++nt) {
                bb[nt * 2 + 0] = g_bv2[cb + nt * 8 + 0];
                bb[nt * 2 + 1] = g_bv2[cb + nt * 8 + 1];
            }
        }
        float d[2][8][4];
        #pragma unroll
        for (int mt = 0; mt < 2; ++mt)
            #pragma unroll
            for (int nt = 0; nt < 8; ++nt)
                #pragma unroll
                for (int e = 0; e < 4; ++e) d[mt][nt][e] = 0.f;

        uint4 ld[4];
        #pragma unroll
        for (int q = 0; q < 4; ++q) {
            int j = q * 256 + tid;
            int n = j >> 3, u = j & 7;
            ld[q] = *(const uint4*)(g_wvb + (size_t)(nbase + n) * HIDDEN + u * 8);
        }
        #pragma unroll
        for (int q = 0; q < 4; ++q) {
            int j = q * 256 + tid;
            int n = j >> 3, u = j & 7;
            *(uint4*)((__nv_bfloat16*)(dsm_v + V_B_OFF) + n * V_B_STRIDE + u * 8) = ld[q];
        }
        __syncthreads();

        for (int kc = 0; kc < 8; ++kc) {
            if (kc < 7) {
                #pragma unroll
                for (int q = 0; q < 4; ++q) {
                    int j = q * 256 + tid;
                    int n = j >> 3, u = j & 7;
                    ld[q] = *(const uint4*)(g_wvb + (size_t)(nbase + n) * HIDDEN + (kc + 1) * 64 + u * 8);
                }
            }
            const uint32_t b_base = smem_to_u32(dsm_v + V_B_OFF + (kc & 1) * V_B_SZ) + (uint32_t)(wn * 64 * V_B_STRIDE) * 2;
            #pragma unroll
            for (int k16 = 0; k16 < 4; ++k16) {
                uint32_t a[2][4];
                #pragma unroll
                for (int mt = 0; mt < 2; ++mt) {
                    uint32_t aaddr = a_base + a_lane +
                        (uint32_t)((wm * 32 + mt * 16) * V_A_STRIDE + kc * 64 + k16 * 16) * 2;
                    LDSM_X4(a[mt], aaddr);
                }
                #pragma unroll
                for (int np = 0; np < 4; ++np) {
                    uint32_t b[4];
                    uint32_t baddr = b_base + b_lane + (uint32_t)(np * 16 * V_B_STRIDE + k16 * 16) * 2;
                    LDSM_X4(b, baddr);
                    MMA16816(d[0][np * 2 + 0], a[0], b[0], b[1]);
                    MMA16816(d[0][np * 2 + 1], a[0], b[2], b[3]);
                    MMA16816(d[1][np * 2 + 0], a[1], b[0], b[1]);
                    MMA16816(d[1][np * 2 + 1], a[1], b[2], b[3]);
                }
            }
            if (kc < 7) {
                __nv_bfloat16* dst = (__nv_bfloat16*)(dsm_v + V_B_OFF + ((kc + 1) & 1) * V_B_SZ);
                #pragma unroll
                for (int q = 0; q < 4; ++q) {
                    int j = q * 256 + tid;
                    int n = j >> 3, u = j & 7;
                    *(uint4*)(dst + n * V_B_STRIDE + u * 8) = ld[q];
                }
            }
            __syncthreads();
        }

        if (!(tt == VTILES - 1 && wn == 1)) {
            #pragma unroll
            for (int mt = 0; mt < 2; ++mt)
                #pragma unroll
                for (int rh = 0; rh < 2; ++rh) {
                    float s = 0.f;
                    #pragma unroll
                    for (int nt = 0; nt < 8; ++nt) {
                        s += exp2_fast(fmaf(d[mt][nt][rh * 2 + 0], LOG2E, bb[nt * 2 + 0]));
                        s += exp2_fast(fmaf(d[mt][nt][rh * 2 + 1], LOG2E, bb[nt * 2 + 1]));
                    }
                    rs[mt][rh] += s;
                }
        }
    }

    float* red = (float*)(dsm_v + V_RED_OFF);
    #pragma unroll
    for (int mt = 0; mt < 2; ++mt)
        #pragma unroll
        for (int rh = 0; rh < 2; ++rh) {
            float v = rs[mt][rh];
            v += __shfl_xor_sync(0xffffffffu, v, 1);
            v += __shfl_xor_sync(0xffffffffu, v, 2);
            if ((lane & 3) == 0) {
                int row = wm * 32 + mt * 16 + rh * 8 + (lane >> 2);
                red[row * 2 + wn] = v;
            }
        }
    __syncthreads();
    if (tid < 128) {
        g_ps[g * MROWS + mblk * 128 + tid] = red[tid * 2 + 0] + red[tid * 2 + 1];
    }
}

// ---------------- combine ----------------
__global__ void __launch_bounds__(1024) combine_kernel(
    const int* __restrict__ captions, float* __restrict__ out)
{
    __shared__ float sh[1024];
    int tid = threadIdx.x;
    float local = 0.f;
    for (int r = tid; r < MROWS; r += 1024) {
        float S = g_ps[r] + g_ps[MROWS + r] + g_ps[2 * MROWS + r] + g_ps[3 * MROWS + r];
        int tg = captions[(r & 15) * 257 + (r >> 4) + 1];
        if (tg != 0) local += logf(S) - g_lt[r];
    }
    sh[tid] = local;
    __syncthreads();
    for (int o = 512; o > 0; o >>= 1) {
        if (tid < o) sh[tid] += sh[tid + o];
        __syncthreads();
    }
    if (tid == 0) out[0] = sh[0] * (1.f / NBATCH);
}

// ---------------- launch ----------------
extern "C" void kernel_launch(void* const* d_in, const int* in_sizes, int n_in,
                              void* d_out, int out_size) {
    const int*   captions = (const int*)d_in[0];
    const float* W_embed  = (const float*)d_in[1];
    const float* Wx       = (const float*)d_in[2];
    const float* Wh       = (const float*)d_in[3];
    const float* b        = (const float*)d_in[4];
    const float* W_vocab  = (const float*)d_in[5];
    const float* b_vocab  = (const float*)d_in[6];
    const float* h_init   = (const float*)d_in[7];

    cudaFuncSetAttribute(lstm_kernel,      cudaFuncAttributeMaxDynamicSharedMemorySize, 83200);
    cudaFuncSetAttribute(vocab_kernel,     cudaFuncAttributeMaxDynamicSharedMemorySize, V_SMEM);
    cudaFuncSetAttribute(embed_mma_kernel, cudaFuncAttributeMaxDynamicSharedMemorySize, E_SMEM);

    init_kernel<<<32, 256>>>(h_init, b_vocab);
    gather_x_kernel<<<256, 256>>>(captions, W_embed);
    conv_wx_kernel<<<dim3(G4 / 32, WORDVEC / 32), 256>>>(Wx);
    conv_wv_kernel<<<dim3(VOCABSZ / 32, HIDDEN / 32), 256>>>(W_vocab);
    embed_mma_kernel<<<512, 256, E_SMEM>>>(b);
    lstm_kernel<<<128, 256, 83200>>>(Wh);
    tgt_kernel<<<512, 256>>>(captions, b_vocab);
    vocab_kernel<<<128, 256, V_SMEM>>>();
    combine_kernel<<<1, 1024>>>(captions, (float*)d_out);
}

// round 11
// speedup vs baseline: 1.9663x; 1.0270x over previous
#include <cuda_runtime.h>
#include <cuda_bf16.h>
#include <cstdint>
#include <math.h>

#define VOCABSZ 32000
#define VPAD    32128
#define WORDVEC 256
#define HIDDEN  512
#define TSTEPS  256
#define NBATCH  16
#define G4      2048
#define MROWS   4096
#define NGRP    4
#define GCOLS   8000
#define VTILES  63
#define LOG2E   1.44269504f

// ---------------- device scratch ----------------
__device__ float          g_xw[TSTEPS * NBATCH * G4];
__device__ float          g_hall[MROWS * HIDDEN];          // [t][n][k] fp32
__device__ __nv_bfloat16  g_hb[MROWS * HIDDEN];            // bf16 copy (written by lstm)
__device__ __nv_bfloat16  g_wvb[(size_t)VPAD * HIDDEN];    // Wv^T bf16 [v][k]
__device__ __nv_bfloat16  g_xb[MROWS * WORDVEC];           // gathered embeddings bf16
__device__ __nv_bfloat16  g_wxT[G4 * WORDVEC];             // Wx^T bf16
__device__ float          g_bv2[VPAD];                     // bv * LOG2E
__device__ uint32_t       g_hpk2[2][NBATCH * HIDDEN];      // packed (hi,lo) bf16 h state [n][k]
__device__ unsigned       g_barc[TSTEPS];                  // barrier counters
__device__ float          g_ps[NGRP * MROWS];
__device__ float          g_lt[MROWS];

// ---------------- helpers ----------------
__device__ __forceinline__ float sigf(float x) { return __fdividef(1.f, 1.f + __expf(-x)); }
__device__ __forceinline__ float tanhf_fast(float x) { return __fdividef(2.f, 1.f + __expf(-2.f * x)) - 1.f; }
__device__ __forceinline__ uint32_t smem_to_u32(const void* p) {
    uint32_t a;
    asm("{ .reg .u64 t; cvta.to.shared.u64 t, %1; cvt.u32.u64 %0, t; }" : "=r"(a) : "l"(p));
    return a;
}
#define LDSM_X4(r, addr) asm volatile( \
    "ldmatrix.sync.aligned.m8n8.x4.shared.b16 {%0,%1,%2,%3}, [%4];" \
    : "=r"((r)[0]), "=r"((r)[1]), "=r"((r)[2]), "=r"((r)[3]) : "r"(addr))
#define MMA16816(d, a, b0, b1) asm volatile( \
    "mma.sync.aligned.m16n8k16.row.col.f32.bf16.bf16.f32 " \
    "{%0,%1,%2,%3}, {%4,%5,%6,%7}, {%8,%9}, {%0,%1,%2,%3};" \
    : "+f"((d)[0]), "+f"((d)[1]), "+f"((d)[2]), "+f"((d)[3]) \
    : "r"((a)[0]), "r"((a)[1]), "r"((a)[2]), "r"((a)[3]), "r"(b0), "r"(b1))

__device__ __forceinline__ float exp2_fast(float t) {
    int i = __float2int_rn(t);
    float f = t - (float)i;
    float p = fmaf(f, 0.00133335581f, 0.00961812911f);
    p = fmaf(f, p, 0.0555041087f);
    p = fmaf(f, p, 0.240226507f);
    p = fmaf(f, p, 0.693147181f);
    p = fmaf(f, p, 1.0f);
    return __int_as_float(__float_as_int(p) + (i << 23));
}

__device__ __forceinline__ void grid_barrier(int idx, unsigned nblocks) {
    __threadfence();
    __syncthreads();
    if (threadIdx.x == 0) {
        atomicAdd(&g_barc[idx], 1u);
        volatile unsigned* p = &g_barc[idx];
        while (*p < nblocks) { }
        __threadfence();
    }
    __syncthreads();
}

// ---------------- init ----------------
__global__ void __launch_bounds__(256) init_kernel(
    const float* __restrict__ h_init, const float* __restrict__ bv)
{
    int gid = blockIdx.x * 256 + threadIdx.x;            // 8192 threads
    if (gid < TSTEPS) g_barc[gid] = 0u;
    if (gid < NBATCH * HIDDEN) {
        int k = gid & 511;
        float v = h_init[k];
        __nv_bfloat16 hi = __float2bfloat16(v);
        float hif = __bfloat162float(hi);
        __nv_bfloat16 lo = __float2bfloat16(v - hif);
        g_hpk2[0][gid] = ((uint32_t)*(uint16_t*)&hi << 16) | *(uint16_t*)&lo;
    }
    for (int j = gid; j < (VPAD - VOCABSZ) * HIDDEN; j += 8192)
        g_wvb[(size_t)VOCABSZ * HIDDEN + j] = __float2bfloat16(0.f);
    for (int j = gid; j < VPAD; j += 8192)
        g_bv2[j] = (j < VOCABSZ) ? bv[j] * LOG2E : 0.f;
}

// ---------------- Wv transpose + bf16 ----------------
__global__ void __launch_bounds__(256) conv_wv_kernel(const float* __restrict__ Wv) {
    __shared__ float sh[32 * 33];
    int n0 = blockIdx.x * 32, k0 = blockIdx.y * 32;
    int tx = threadIdx.x & 31, ty = threadIdx.x >> 5;
    #pragma unroll
    for (int i = 0; i < 4; ++i) {
        int k = ty + i * 8;
        sh[k * 33 + tx] = Wv[(size_t)(k0 + k) * VOCABSZ + n0 + tx];
    }
    __syncthreads();
    #pragma unroll
    for (int i = 0; i < 4; ++i) {
        int n = ty + i * 8;
        g_wvb[(size_t)(n0 + n) * HIDDEN + k0 + tx] = __float2bfloat16(sh[tx * 33 + n]);
    }
}

// ---------------- Wx transpose + bf16 ----------------
__global__ void __launch_bounds__(256) conv_wx_kernel(const float* __restrict__ Wx) {
    __shared__ float sh[32 * 33];
    int n0 = blockIdx.x * 32, k0 = blockIdx.y * 32;
    int tx = threadIdx.x & 31, ty = threadIdx.x >> 5;
    #pragma unroll
    for (int i = 0; i < 4; ++i) {
        int k = ty + i * 8;
        sh[k * 33 + tx] = Wx[(k0 + k) * G4 + n0 + tx];
    }
    __syncthreads();
    #pragma unroll
    for (int i = 0; i < 4; ++i) {
        int n = ty + i * 8;
        g_wxT[(n0 + n) * WORDVEC + k0 + tx] = __float2bfloat16(sh[tx * 33 + n]);
    }
}

// ---------------- gather embeddings -> bf16 ----------------
__global__ void __launch_bounds__(256) gather_x_kernel(
    const int* __restrict__ captions, const float* __restrict__ W_embed)
{
    int gid = blockIdx.x * 256 + threadIdx.x;
    int idx = gid * 4;
    int r = idx >> 8, d = idx & 255;
    int tok = captions[(r & 15) * 257 + (r >> 4)];
    float4 v = *(const float4*)&W_embed[tok * WORDVEC + d];
    __nv_bfloat16 o[4];
    o[0] = __float2bfloat16(v.x); o[1] = __float2bfloat16(v.y);
    o[2] = __float2bfloat16(v.z); o[3] = __float2bfloat16(v.w);
    *(uint2*)&g_xb[idx] = *(const uint2*)o;
}

// ---------------- embed GEMM (bf16 mma.sync) ----------------
#define E_A_STRIDE 264
#define E_B_OFF    67584
#define E_SMEM     135168
extern __shared__ __align__(16) char dsm_e[];
__global__ void __launch_bounds__(256, 1) embed_mma_kernel(const float* __restrict__ b) {
    __nv_bfloat16* As = (__nv_bfloat16*)dsm_e;
    __nv_bfloat16* Bs = (__nv_bfloat16*)(dsm_e + E_B_OFF);
    const int tid = threadIdx.x, lane = tid & 31, wid = tid >> 5;
    const int wm = wid >> 1, wn = wid & 1;
    const int mblk = blockIdx.x >> 4, nblk = blockIdx.x & 15;

    const uint4* asrc = (const uint4*)(g_xb + mblk * 128 * WORDVEC);
    const uint4* bsrc = (const uint4*)(g_wxT + nblk * 128 * WORDVEC);
    #pragma unroll
    for (int q = 0; q < 16; ++q) {
        int i = q * 256 + tid;
        int r = i >> 5, u = i & 31;
        *(uint4*)(As + r * E_A_STRIDE + u * 8) = asrc[i];
        *(uint4*)(Bs + r * E_A_STRIDE + u * 8) = bsrc[i];
    }
    __syncthreads();

    const uint32_t a_base = smem_to_u32(As);
    const uint32_t a_lane = (uint32_t)((lane & 15) * E_A_STRIDE + (lane >> 4) * 8) * 2;
    const int bq = lane >> 3;
    const uint32_t b_lane = (uint32_t)(((bq >> 1) * 8 + (lane & 7)) * E_A_STRIDE + (bq & 1) * 8) * 2;
    const uint32_t b_base = smem_to_u32(Bs) + (uint32_t)(wn * 64 * E_A_STRIDE) * 2;

    float d[2][8][4];
    #pragma unroll
    for (int mt = 0; mt < 2; ++mt)
        #pragma unroll
        for (int nt = 0; nt < 8; ++nt)
            #pragma unroll
            for (int e = 0; e < 4; ++e) d[mt][nt][e] = 0.f;

    #pragma unroll
    for (int k16 = 0; k16 < 16; ++k16) {
        const uint32_t koff = (uint32_t)(k16 * 16) * 2;
        uint32_t a[2][4];
        #pragma unroll
        for (int mt = 0; mt < 2; ++mt) {
            LDSM_X4(a[mt], a_base + a_lane + (uint32_t)((wm * 32 + mt * 16) * E_A_STRIDE) * 2 + koff);
        }
        #pragma unroll
        for (int np = 0; np < 4; ++np) {
            uint32_t bb[4];
            LDSM_X4(bb, b_base + b_lane + (uint32_t)(np * 16 * E_A_STRIDE) * 2 + koff);
            MMA16816(d[0][np * 2 + 0], a[0], bb[0], bb[1]);
            MMA16816(d[0][np * 2 + 1], a[0], bb[2], bb[3]);
            MMA16816(d[1][np * 2 + 0], a[1], bb[0], bb[1]);
            MMA16816(d[1][np * 2 + 1], a[1], bb[2], bb[3]);
        }
    }

    const int cbase = nblk * 128 + wn * 64 + (lane & 3) * 2;
    #pragma unroll
    for (int mt = 0; mt < 2; ++mt)
        #pragma unroll
        for (int rh = 0; rh < 2; ++rh) {
            int row = mblk * 128 + wm * 32 + mt * 16 + rh * 8 + (lane >> 2);
            #pragma unroll
            for (int nt = 0; nt < 8; ++nt) {
                int c = cbase + nt * 8;
                float2 v;
                v.x = d[mt][nt][rh * 2 + 0] + b[c];
                v.y = d[mt][nt][rh * 2 + 1] + b[c + 1];
                *(float2*)&g_xw[(size_t)row * G4 + c] = v;
            }
        }
}

// ---------------- persistent LSTM v2: tensor-core h@Wh via hi/lo bf16 split ------------
// 32 blocks x 256 threads. Block owns 16 hidden units (all 4 gates):
// j-cols g*512 + bid*16 + q. Wh hi/lo tiles [64 rows][512 k] in SMEM.
// 4 mma warps: warp w covers rows w*16..w*16+15 (n16), full K=512 -> no reduction.
#define L_BH   0
#define L_BL   66560
#define L_AH   133120
#define L_AL   149760
#define L_ASH  166400
#define L_CSH  170752
#define L_SMEM 171776
extern __shared__ __align__(16) char dsm_l[];
__global__ void __launch_bounds__(256, 1) lstm_kernel(const float* __restrict__ Wh) {
    const int bid = blockIdx.x, tid = threadIdx.x;
    const int lane = tid & 31, wid = tid >> 5;
    uint16_t* Bh = (uint16_t*)(dsm_l + L_BH);
    uint16_t* Bl = (uint16_t*)(dsm_l + L_BL);
    uint16_t* Ah = (uint16_t*)(dsm_l + L_AH);
    uint16_t* Al = (uint16_t*)(dsm_l + L_AL);
    float* a_sh = (float*)(dsm_l + L_ASH);   // [64 rows][17]
    float* c_sh = (float*)(dsm_l + L_CSH);   // [256]

    // one-time: split Wh slice into hi/lo bf16 tiles (rows r=g*16+q, k)
    for (int i = tid; i < 64 * 512; i += 256) {
        int k = i >> 6, r = i & 63;
        int jcol = (r >> 4) * 512 + bid * 16 + (r & 15);
        float w = Wh[k * G4 + jcol];
        __nv_bfloat16 hi = __float2bfloat16(w);
        float hif = __bfloat162float(hi);
        __nv_bfloat16 lo = __float2bfloat16(w - hif);
        Bh[r * 520 + k] = *(uint16_t*)&hi;
        Bl[r * 520 + k] = *(uint16_t*)&lo;
    }
    c_sh[tid] = 0.f;

    const int q = tid & 15, n = tid >> 4;
    const int jglob = bid * 16 + q;

    const uint32_t a_base_h = smem_to_u32(dsm_l + L_AH);
    const uint32_t a_base_l = smem_to_u32(dsm_l + L_AL);
    const uint32_t a_lane = (uint32_t)((lane & 15) * 520 + (lane >> 4) * 8) * 2;
    const int bq = lane >> 3;
    const uint32_t b_lane = (uint32_t)((wid * 16 + (bq >> 1) * 8 + (lane & 7)) * 520 + (bq & 1) * 8) * 2;
    const uint32_t b_base_h = smem_to_u32(dsm_l + L_BH) + b_lane;
    const uint32_t b_base_l = smem_to_u32(dsm_l + L_BL) + b_lane;

    for (int t = 0; t < TSTEPS; ++t) {
        // A fill: unpack (hi,lo) h state into two bf16 smem tiles [16][520]
        const uint32_t* src = (const uint32_t*)g_hpk2[t & 1];
        #pragma unroll
        for (int j = 0; j < 32; ++j) {
            int idx = tid + j * 256;
            int an = idx >> 9, ak = idx & 511;
            uint32_t u = __ldcg(&src[idx]);
            Ah[an * 520 + ak] = (uint16_t)(u >> 16);
            Al[an * 520 + ak] = (uint16_t)(u & 0xffffu);
        }
        float xwv[4];
        #pragma unroll
        for (int g = 0; g < 4; ++g)
            xwv[g] = g_xw[(size_t)(t * NBATCH + n) * G4 + g * 512 + jglob];
        __syncthreads();

        if (wid < 4) {
            float d[6][4];
            #pragma unroll
            for (int i = 0; i < 6; ++i)
                #pragma unroll
                for (int e = 0; e < 4; ++e) d[i][e] = 0.f;

            #pragma unroll 8
            for (int s = 0; s < 32; ++s) {
                uint32_t koff = (uint32_t)(s * 16) * 2;
                uint32_t ah[4], al[4], bh[4], bl[4];
                LDSM_X4(ah, a_base_h + a_lane + koff);
                LDSM_X4(al, a_base_l + a_lane + koff);
                LDSM_X4(bh, b_base_h + koff);
                LDSM_X4(bl, b_base_l + koff);
                MMA16816(d[0], ah, bh[0], bh[1]);
                MMA16816(d[1], ah, bl[0], bl[1]);
                MMA16816(d[2], al, bh[0], bh[1]);
                MMA16816(d[3], ah, bh[2], bh[3]);
                MMA16816(d[4], ah, bl[2], bl[3]);
                MMA16816(d[5], al, bh[2], bh[3]);
            }
            int m0 = lane >> 2, cc = 2 * (lane & 3);
            int r0 = wid * 16 + cc;
            int r1 = wid * 16 + 8 + cc;
            float e0[4], e1[4];
            #pragma unroll
            for (int e = 0; e < 4; ++e) {
                e0[e] = d[0][e] + d[1][e] + d[2][e];
                e1[e] = d[3][e] + d[4][e] + d[5][e];
            }
            a_sh[(r0 + 0) * 17 + m0]     = e0[0];
            a_sh[(r0 + 1) * 17 + m0]     = e0[1];
            a_sh[(r0 + 0) * 17 + m0 + 8] = e0[2];
            a_sh[(r0 + 1) * 17 + m0 + 8] = e0[3];
            a_sh[(r1 + 0) * 17 + m0]     = e1[0];
            a_sh[(r1 + 1) * 17 + m0]     = e1[1];
            a_sh[(r1 + 0) * 17 + m0 + 8] = e1[2];
            a_sh[(r1 + 1) * 17 + m0 + 8] = e1[3];
        }
        __syncthreads();

        // gate update: one (n, q) per thread
        {
            float av0 = a_sh[( 0 + q) * 17 + n] + xwv[0];
            float av1 = a_sh[(16 + q) * 17 + n] + xwv[1];
            float av2 = a_sh[(32 + q) * 17 + n] + xwv[2];
            float av3 = a_sh[(48 + q) * 17 + n] + xwv[3];
            float ig = sigf(av0), fg = sigf(av1), og = sigf(av2), gg = tanhf_fast(av3);
            float c  = fg * c_sh[tid] + ig * gg;
            float hh = og * tanhf_fast(c);
            c_sh[tid] = c;
            __nv_bfloat16 hi = __float2bfloat16(hh);
            float hif = __bfloat162float(hi);
            __nv_bfloat16 lo = __float2bfloat16(hh - hif);
            g_hpk2[(t & 1) ^ 1][n * HIDDEN + jglob] =
                ((uint32_t)*(uint16_t*)&hi << 16) | *(uint16_t*)&lo;
            g_hall[t * (NBATCH * HIDDEN) + n * HIDDEN + jglob] = hh;
            g_hb[t * (NBATCH * HIDDEN) + n * HIDDEN + jglob] = hi;
        }
        grid_barrier(t, 32);
    }
}

// ---------------- target logits ----------------
__global__ void __launch_bounds__(256) tgt_kernel(
    const int* __restrict__ captions, const float* __restrict__ bv)
{
    int wid = threadIdx.x >> 5, lane = threadIdx.x & 31;
    int r = blockIdx.x * 8 + wid;
    int tg = captions[(r & 15) * 257 + (r >> 4) + 1];
    const float* hr = &g_hall[r * HIDDEN];
    const __nv_bfloat16* wv = &g_wvb[(size_t)tg * HIDDEN];
    float s = 0.f;
    #pragma unroll
    for (int i = 0; i < 16; ++i) {
        int k = lane + i * 32;
        s = fmaf(hr[k], __bfloat162float(wv[k]), s);
    }
    #pragma unroll
    for (int o = 16; o > 0; o >>= 1) s += __shfl_xor_sync(0xffffffffu, s, o);
    if (lane == 0) g_lt[r] = s + bv[tg];
}

// ---------------- vocab: bf16 mma.sync + streaming exp-sum ----------------
#define V_A_STRIDE 520
#define V_B_OFF    133120
#define V_B_SZ     18432
#define V_B_STRIDE 72
#define V_RED_OFF  169984
#define V_SMEM     171008
extern __shared__ __align__(16) char dsm_v[];
__global__ void __launch_bounds__(256, 1) vocab_kernel() {
    __nv_bfloat16* As = (__nv_bfloat16*)dsm_v;
    const int tid = threadIdx.x, lane = tid & 31, wid = tid >> 5;
    const int wm = wid >> 1, wn = wid & 1;
    const int mblk = blockIdx.x >> 2, g = blockIdx.x & 3;
    const int gbase = g * GCOLS;

    {
        const uint4* src = (const uint4*)(g_hb + (size_t)(mblk * 128) * HIDDEN);
        for (int i = tid; i < 8192; i += 256) {
            int r = i >> 6, u = i & 63;
            *(uint4*)(As + r * V_A_STRIDE + u * 8) = src[i];
        }
    }
    __syncthreads();

    const uint32_t a_base = smem_to_u32(dsm_v);
    const uint32_t a_lane = (uint32_t)((lane & 15) * V_A_STRIDE + (lane >> 4) * 8) * 2;
    const int bq = lane >> 3;
    const uint32_t b_lane = (uint32_t)(((bq >> 1) * 8 + (lane & 7)) * V_B_STRIDE + (bq & 1) * 8) * 2;

    float rs[2][2] = {{0.f, 0.f}, {0.f, 0.f}};

    for (int tt = 0; tt < VTILES; ++tt) {
        const int nbase = gbase + tt * 128;
        float bb[16];
        {
            int cb = nbase + wn * 64 + (lane & 3) * 2;
            #pragma unroll
            for (int nt = 0; nt < 8; ++nt) {
                bb[nt * 2 + 0] = g_bv2[cb + nt * 8 + 0];
                bb[nt * 2 + 1] = g_bv2[cb + nt * 8 + 1];
            }
        }
        float d[2][8][4];
        #pragma unroll
        for (int mt = 0; mt < 2; ++mt)
            #pragma unroll
            for (int nt = 0; nt < 8; ++nt)
                #pragma unroll
                for (int e = 0; e < 4; ++e) d[mt][nt][e] = 0.f;

        uint4 ld[4];
        #pragma unroll
        for (int q = 0; q < 4; ++q) {
            int j = q * 256 + tid;
            int n = j >> 3, u = j & 7;
            ld[q] = *(const uint4*)(g_wvb + (size_t)(nbase + n) * HIDDEN + u * 8);
        }
        #pragma unroll
        for (int q = 0; q < 4; ++q) {
            int j = q * 256 + tid;
            int n = j >> 3, u = j & 7;
            *(uint4*)((__nv_bfloat16*)(dsm_v + V_B_OFF) + n * V_B_STRIDE + u * 8) = ld[q];
        }
        __syncthreads();

        for (int kc = 0; kc < 8; ++kc) {
            if (kc < 7) {
                #pragma unroll
                for (int q = 0; q < 4; ++q) {
                    int j = q * 256 + tid;
                    int n = j >> 3, u = j & 7;
                    ld[q] = *(const uint4*)(g_wvb + (size_t)(nbase + n) * HIDDEN + (kc + 1) * 64 + u * 8);
                }
            }
            const uint32_t b_base = smem_to_u32(dsm_v + V_B_OFF + (kc & 1) * V_B_SZ) + (uint32_t)(wn * 64 * V_B_STRIDE) * 2;
            #pragma unroll
            for (int k16 = 0; k16 < 4; ++k16) {
                uint32_t a[2][4];
                #pragma unroll
                for (int mt = 0; mt < 2; ++mt) {
                    uint32_t aaddr = a_base + a_lane +
                        (uint32_t)((wm * 32 + mt * 16) * V_A_STRIDE + kc * 64 + k16 * 16) * 2;
                    LDSM_X4(a[mt], aaddr);
                }
                #pragma unroll
                for (int np = 0; np < 4; ++np) {
                    uint32_t b[4];
                    uint32_t baddr = b_base + b_lane + (uint32_t)(np * 16 * V_B_STRIDE + k16 * 16) * 2;
                    LDSM_X4(b, baddr);
                    MMA16816(d[0][np * 2 + 0], a[0], b[0], b[1]);
                    MMA16816(d[0][np * 2 + 1], a[0], b[2], b[3]);
                    MMA16816(d[1][np * 2 + 0], a[1], b[0], b[1]);
                    MMA16816(d[1][np * 2 + 1], a[1], b[2], b[3]);
                }
            }
            if (kc < 7) {
                __nv_bfloat16* dst = (__nv_bfloat16*)(dsm_v + V_B_OFF + ((kc + 1) & 1) * V_B_SZ);
                #pragma unroll
                for (int q = 0; q < 4; ++q) {
                    int j = q * 256 + tid;
                    int n = j >> 3, u = j & 7;
                    *(uint4*)(dst + n * V_B_STRIDE + u * 8) = ld[q];
                }
            }
            __syncthreads();
        }

        if (!(tt == VTILES - 1 && wn == 1)) {
            #pragma unroll
            for (int mt = 0; mt < 2; ++mt)
                #pragma unroll
                for (int rh = 0; rh < 2; ++rh) {
                    float s = 0.f;
                    #pragma unroll
                    for (int nt = 0; nt < 8; ++nt) {
                        s += exp2_fast(fmaf(d[mt][nt][rh * 2 + 0], LOG2E, bb[nt * 2 + 0]));
                        s += exp2_fast(fmaf(d[mt][nt][rh * 2 + 1], LOG2E, bb[nt * 2 + 1]));
                    }
                    rs[mt][rh] += s;
                }
        }
    }

    float* red = (float*)(dsm_v + V_RED_OFF);
    #pragma unroll
    for (int mt = 0; mt < 2; ++mt)
        #pragma unroll
        for (int rh = 0; rh < 2; ++rh) {
            float v = rs[mt][rh];
            v += __shfl_xor_sync(0xffffffffu, v, 1);
            v += __shfl_xor_sync(0xffffffffu, v, 2);
            if ((lane & 3) == 0) {
                int row = wm * 32 + mt * 16 + rh * 8 + (lane >> 2);
                red[row * 2 + wn] = v;
            }
        }
    __syncthreads();
    if (tid < 128) {
        g_ps[g * MROWS + mblk * 128 + tid] = red[tid * 2 + 0] + red[tid * 2 + 1];
    }
}

// ---------------- combine ----------------
__global__ void __launch_bounds__(1024) combine_kernel(
    const int* __restrict__ captions, float* __restrict__ out)
{
    __shared__ float sh[1024];
    int tid = threadIdx.x;
    float local = 0.f;
    for (int r = tid; r < MROWS; r += 1024) {
        float S = g_ps[r] + g_ps[MROWS + r] + g_ps[2 * MROWS + r] + g_ps[3 * MROWS + r];
        int tg = captions[(r & 15) * 257 + (r >> 4) + 1];
        if (tg != 0) local += logf(S) - g_lt[r];
    }
    sh[tid] = local;
    __syncthreads();
    for (int o = 512; o > 0; o >>= 1) {
        if (tid < o) sh[tid] += sh[tid + o];
        __syncthreads();
    }
    if (tid == 0) out[0] = sh[0] * (1.f / NBATCH);
}

// ---------------- launch ----------------
extern "C" void kernel_launch(void* const* d_in, const int* in_sizes, int n_in,
                              void* d_out, int out_size) {
    const int*   captions = (const int*)d_in[0];
    const float* W_embed  = (const float*)d_in[1];
    const float* Wx       = (const float*)d_in[2];
    const float* Wh       = (const float*)d_in[3];
    const float* b        = (const float*)d_in[4];
    const float* W_vocab  = (const float*)d_in[5];
    const float* b_vocab  = (const float*)d_in[6];
    const float* h_init   = (const float*)d_in[7];

    cudaFuncSetAttribute(lstm_kernel,      cudaFuncAttributeMaxDynamicSharedMemorySize, L_SMEM);
    cudaFuncSetAttribute(vocab_kernel,     cudaFuncAttributeMaxDynamicSharedMemorySize, V_SMEM);
    cudaFuncSetAttribute(embed_mma_kernel, cudaFuncAttributeMaxDynamicSharedMemorySize, E_SMEM);

    init_kernel<<<32, 256>>>(h_init, b_vocab);
    gather_x_kernel<<<256, 256>>>(captions, W_embed);
    conv_wx_kernel<<<dim3(G4 / 32, WORDVEC / 32), 256>>>(Wx);
    conv_wv_kernel<<<dim3(VOCABSZ / 32, HIDDEN / 32), 256>>>(W_vocab);
    embed_mma_kernel<<<512, 256, E_SMEM>>>(b);
    lstm_kernel<<<32, 256, L_SMEM>>>(Wh);
    tgt_kernel<<<512, 256>>>(captions, b_vocab);
    vocab_kernel<<<128, 256, V_SMEM>>>();
    combine_kernel<<<1, 1024>>>(captions, (float*)d_out);
}

// round 12
// speedup vs baseline: 1.9686x; 1.0012x over previous
#include <cuda_runtime.h>
#include <cuda_bf16.h>
#include <cstdint>
#include <math.h>

#define VOCABSZ 32000
#define VPAD    32128
#define WORDVEC 256
#define HIDDEN  512
#define TSTEPS  256
#define NBATCH  16
#define G4      2048
#define MROWS   4096
#define NGRP    4
#define GCOLS   8000
#define VTILES  63
#define LOG2E   1.44269504f

// ---------------- device scratch ----------------
__device__ float          g_xw[TSTEPS * NBATCH * G4];
__device__ float          g_hall[MROWS * HIDDEN];          // [t][n][k] fp32
__device__ __nv_bfloat16  g_hb[MROWS * HIDDEN];            // bf16 copy (written by lstm)
__device__ __nv_bfloat16  g_wvb[(size_t)VPAD * HIDDEN];    // Wv^T bf16 [v][k]
__device__ __nv_bfloat16  g_xb[MROWS * WORDVEC];           // gathered embeddings bf16
__device__ __nv_bfloat16  g_wxT[G4 * WORDVEC];             // Wx^T bf16
__device__ float          g_bv2[VPAD];                     // bv * LOG2E
__device__ uint32_t       g_hpk2[2][NBATCH * HIDDEN];      // packed (hi,lo) bf16 h state [n][k]
__device__ unsigned       g_barc[TSTEPS];                  // barrier counters
__device__ float          g_ps[NGRP * MROWS];
__device__ float          g_lt[MROWS];

// ---------------- helpers ----------------
__device__ __forceinline__ float sigf(float x) { return __fdividef(1.f, 1.f + __expf(-x)); }
__device__ __forceinline__ float tanhf_fast(float x) { return __fdividef(2.f, 1.f + __expf(-2.f * x)) - 1.f; }
__device__ __forceinline__ uint32_t smem_to_u32(const void* p) {
    uint32_t a;
    asm("{ .reg .u64 t; cvta.to.shared.u64 t, %1; cvt.u32.u64 %0, t; }" : "=r"(a) : "l"(p));
    return a;
}
#define LDSM_X4(r, addr) asm volatile( \
    "ldmatrix.sync.aligned.m8n8.x4.shared.b16 {%0,%1,%2,%3}, [%4];" \
    : "=r"((r)[0]), "=r"((r)[1]), "=r"((r)[2]), "=r"((r)[3]) : "r"(addr))
#define MMA16816(d, a, b0, b1) asm volatile( \
    "mma.sync.aligned.m16n8k16.row.col.f32.bf16.bf16.f32 " \
    "{%0,%1,%2,%3}, {%4,%5,%6,%7}, {%8,%9}, {%0,%1,%2,%3};" \
    : "+f"((d)[0]), "+f"((d)[1]), "+f"((d)[2]), "+f"((d)[3]) \
    : "r"((a)[0]), "r"((a)[1]), "r"((a)[2]), "r"((a)[3]), "r"(b0), "r"(b1))

__device__ __forceinline__ float exp2_fast(float t) {
    int i = __float2int_rn(t);
    float f = t - (float)i;
    float p = fmaf(f, 0.00133335581f, 0.00961812911f);
    p = fmaf(f, p, 0.0555041087f);
    p = fmaf(f, p, 0.240226507f);
    p = fmaf(f, p, 0.693147181f);
    p = fmaf(f, p, 1.0f);
    return __int_as_float(__float_as_int(p) + (i << 23));
}

__device__ __forceinline__ void grid_barrier(int idx, unsigned nblocks) {
    __threadfence();
    __syncthreads();
    if (threadIdx.x == 0) {
        atomicAdd(&g_barc[idx], 1u);
        volatile unsigned* p = &g_barc[idx];
        while (*p < nblocks) { }
        __threadfence();
    }
    __syncthreads();
}

// ---------------- init ----------------
__global__ void __launch_bounds__(256) init_kernel(
    const float* __restrict__ h_init, const float* __restrict__ bv)
{
    int gid = blockIdx.x * 256 + threadIdx.x;            // 8192 threads
    if (gid < TSTEPS) g_barc[gid] = 0u;
    if (gid < NBATCH * HIDDEN) {
        int k = gid & 511;
        float v = h_init[k];
        __nv_bfloat16 hi = __float2bfloat16(v);
        float hif = __bfloat162float(hi);
        __nv_bfloat16 lo = __float2bfloat16(v - hif);
        g_hpk2[0][gid] = ((uint32_t)*(uint16_t*)&hi << 16) | *(uint16_t*)&lo;
    }
    for (int j = gid; j < (VPAD - VOCABSZ) * HIDDEN; j += 8192)
        g_wvb[(size_t)VOCABSZ * HIDDEN + j] = __float2bfloat16(0.f);
    for (int j = gid; j < VPAD; j += 8192)
        g_bv2[j] = (j < VOCABSZ) ? bv[j] * LOG2E : 0.f;
}

// ---------------- Wv transpose + bf16 ----------------
__global__ void __launch_bounds__(256) conv_wv_kernel(const float* __restrict__ Wv) {
    __shared__ float sh[32 * 33];
    int n0 = blockIdx.x * 32, k0 = blockIdx.y * 32;
    int tx = threadIdx.x & 31, ty = threadIdx.x >> 5;
    #pragma unroll
    for (int i = 0; i < 4; ++i) {
        int k = ty + i * 8;
        sh[k * 33 + tx] = Wv[(size_t)(k0 + k) * VOCABSZ + n0 + tx];
    }
    __syncthreads();
    #pragma unroll
    for (int i = 0; i < 4; ++i) {
        int n = ty + i * 8;
        g_wvb[(size_t)(n0 + n) * HIDDEN + k0 + tx] = __float2bfloat16(sh[tx * 33 + n]);
    }
}

// ---------------- Wx transpose + bf16 ----------------
__global__ void __launch_bounds__(256) conv_wx_kernel(const float* __restrict__ Wx) {
    __shared__ float sh[32 * 33];
    int n0 = blockIdx.x * 32, k0 = blockIdx.y * 32;
    int tx = threadIdx.x & 31, ty = threadIdx.x >> 5;
    #pragma unroll
    for (int i = 0; i < 4; ++i) {
        int k = ty + i * 8;
        sh[k * 33 + tx] = Wx[(k0 + k) * G4 + n0 + tx];
    }
    __syncthreads();
    #pragma unroll
    for (int i = 0; i < 4; ++i) {
        int n = ty + i * 8;
        g_wxT[(n0 + n) * WORDVEC + k0 + tx] = __float2bfloat16(sh[tx * 33 + n]);
    }
}

// ---------------- gather embeddings -> bf16 ----------------
__global__ void __launch_bounds__(256) gather_x_kernel(
    const int* __restrict__ captions, const float* __restrict__ W_embed)
{
    int gid = blockIdx.x * 256 + threadIdx.x;
    int idx = gid * 4;
    int r = idx >> 8, d = idx & 255;
    int tok = captions[(r & 15) * 257 + (r >> 4)];
    float4 v = *(const float4*)&W_embed[tok * WORDVEC + d];
    __nv_bfloat16 o[4];
    o[0] = __float2bfloat16(v.x); o[1] = __float2bfloat16(v.y);
    o[2] = __float2bfloat16(v.z); o[3] = __float2bfloat16(v.w);
    *(uint2*)&g_xb[idx] = *(const uint2*)o;
}

// ---------------- embed GEMM (bf16 mma.sync) ----------------
#define E_A_STRIDE 264
#define E_B_OFF    67584
#define E_SMEM     135168
extern __shared__ __align__(16) char dsm_e[];
__global__ void __launch_bounds__(256, 1) embed_mma_kernel(const float* __restrict__ b) {
    __nv_bfloat16* As = (__nv_bfloat16*)dsm_e;
    __nv_bfloat16* Bs = (__nv_bfloat16*)(dsm_e + E_B_OFF);
    const int tid = threadIdx.x, lane = tid & 31, wid = tid >> 5;
    const int wm = wid >> 1, wn = wid & 1;
    const int mblk = blockIdx.x >> 4, nblk = blockIdx.x & 15;

    const uint4* asrc = (const uint4*)(g_xb + mblk * 128 * WORDVEC);
    const uint4* bsrc = (const uint4*)(g_wxT + nblk * 128 * WORDVEC);
    #pragma unroll
    for (int q = 0; q < 16; ++q) {
        int i = q * 256 + tid;
        int r = i >> 5, u = i & 31;
        *(uint4*)(As + r * E_A_STRIDE + u * 8) = asrc[i];
        *(uint4*)(Bs + r * E_A_STRIDE + u * 8) = bsrc[i];
    }
    __syncthreads();

    const uint32_t a_base = smem_to_u32(As);
    const uint32_t a_lane = (uint32_t)((lane & 15) * E_A_STRIDE + (lane >> 4) * 8) * 2;
    const int bq = lane >> 3;
    const uint32_t b_lane = (uint32_t)(((bq >> 1) * 8 + (lane & 7)) * E_A_STRIDE + (bq & 1) * 8) * 2;
    const uint32_t b_base = smem_to_u32(Bs) + (uint32_t)(wn * 64 * E_A_STRIDE) * 2;

    float d[2][8][4];
    #pragma unroll
    for (int mt = 0; mt < 2; ++mt)
        #pragma unroll
        for (int nt = 0; nt < 8; ++nt)
            #pragma unroll
            for (int e = 0; e < 4; ++e) d[mt][nt][e] = 0.f;

    #pragma unroll
    for (int k16 = 0; k16 < 16; ++k16) {
        const uint32_t koff = (uint32_t)(k16 * 16) * 2;
        uint32_t a[2][4];
        #pragma unroll
        for (int mt = 0; mt < 2; ++mt) {
            LDSM_X4(a[mt], a_base + a_lane + (uint32_t)((wm * 32 + mt * 16) * E_A_STRIDE) * 2 + koff);
        }
        #pragma unroll
        for (int np = 0; np < 4; ++np) {
            uint32_t bb[4];
            LDSM_X4(bb, b_base + b_lane + (uint32_t)(np * 16 * E_A_STRIDE) * 2 + koff);
            MMA16816(d[0][np * 2 + 0], a[0], bb[0], bb[1]);
            MMA16816(d[0][np * 2 + 1], a[0], bb[2], bb[3]);
            MMA16816(d[1][np * 2 + 0], a[1], bb[0], bb[1]);
            MMA16816(d[1][np * 2 + 1], a[1], bb[2], bb[3]);
        }
    }

    const int cbase = nblk * 128 + wn * 64 + (lane & 3) * 2;
    #pragma unroll
    for (int mt = 0; mt < 2; ++mt)
        #pragma unroll
        for (int rh = 0; rh < 2; ++rh) {
            int row = mblk * 128 + wm * 32 + mt * 16 + rh * 8 + (lane >> 2);
            #pragma unroll
            for (int nt = 0; nt < 8; ++nt) {
                int c = cbase + nt * 8;
                float2 v;
                v.x = d[mt][nt][rh * 2 + 0] + b[c];
                v.y = d[mt][nt][rh * 2 + 1] + b[c + 1];
                *(float2*)&g_xw[(size_t)row * G4 + c] = v;
            }
        }
}

// ---------------- persistent LSTM v2: tensor-core h@Wh via hi/lo bf16 split ------------
// 32 blocks x 256 threads. Block owns 16 hidden units (all 4 gates):
// j-cols g*512 + bid*16 + q. Wh hi/lo tiles [64 rows][512 k] in SMEM.
// 4 mma warps: warp w covers rows w*16..w*16+15 (n16), full K=512 -> no reduction.
#define L_BH   0
#define L_BL   66560
#define L_AH   133120
#define L_AL   149760
#define L_ASH  166400
#define L_CSH  170752
#define L_SMEM 171776
extern __shared__ __align__(16) char dsm_l[];
__global__ void __launch_bounds__(256, 1) lstm_kernel(const float* __restrict__ Wh) {
    const int bid = blockIdx.x, tid = threadIdx.x;
    const int lane = tid & 31, wid = tid >> 5;
    uint16_t* Bh = (uint16_t*)(dsm_l + L_BH);
    uint16_t* Bl = (uint16_t*)(dsm_l + L_BL);
    uint16_t* Ah = (uint16_t*)(dsm_l + L_AH);
    uint16_t* Al = (uint16_t*)(dsm_l + L_AL);
    float* a_sh = (float*)(dsm_l + L_ASH);   // [64 rows][17]
    float* c_sh = (float*)(dsm_l + L_CSH);   // [256]

    // one-time: split Wh slice into hi/lo bf16 tiles (rows r=g*16+q, k)
    for (int i = tid; i < 64 * 512; i += 256) {
        int k = i >> 6, r = i & 63;
        int jcol = (r >> 4) * 512 + bid * 16 + (r & 15);
        float w = Wh[k * G4 + jcol];
        __nv_bfloat16 hi = __float2bfloat16(w);
        float hif = __bfloat162float(hi);
        __nv_bfloat16 lo = __float2bfloat16(w - hif);
        Bh[r * 520 + k] = *(uint16_t*)&hi;
        Bl[r * 520 + k] = *(uint16_t*)&lo;
    }
    c_sh[tid] = 0.f;

    const int q = tid & 15, n = tid >> 4;
    const int jglob = bid * 16 + q;

    const uint32_t a_base_h = smem_to_u32(dsm_l + L_AH);
    const uint32_t a_base_l = smem_to_u32(dsm_l + L_AL);
    const uint32_t a_lane = (uint32_t)((lane & 15) * 520 + (lane >> 4) * 8) * 2;
    const int bq = lane >> 3;
    const uint32_t b_lane = (uint32_t)((wid * 16 + (bq >> 1) * 8 + (lane & 7)) * 520 + (bq & 1) * 8) * 2;
    const uint32_t b_base_h = smem_to_u32(dsm_l + L_BH) + b_lane;
    const uint32_t b_base_l = smem_to_u32(dsm_l + L_BL) + b_lane;

    for (int t = 0; t < TSTEPS; ++t) {
        // A fill: unpack (hi,lo) h state into two bf16 smem tiles [16][520]
        const uint32_t* src = (const uint32_t*)g_hpk2[t & 1];
        #pragma unroll
        for (int j = 0; j < 32; ++j) {
            int idx = tid + j * 256;
            int an = idx >> 9, ak = idx & 511;
            uint32_t u = __ldcg(&src[idx]);
            Ah[an * 520 + ak] = (uint16_t)(u >> 16);
            Al[an * 520 + ak] = (uint16_t)(u & 0xffffu);
        }
        float xwv[4];
        #pragma unroll
        for (int g = 0; g < 4; ++g)
            xwv[g] = g_xw[(size_t)(t * NBATCH + n) * G4 + g * 512 + jglob];
        __syncthreads();

        if (wid < 4) {
            float d[6][4];
            #pragma unroll
            for (int i = 0; i < 6; ++i)
                #pragma unroll
                for (int e = 0; e < 4; ++e) d[i][e] = 0.f;

            #pragma unroll 8
            for (int s = 0; s < 32; ++s) {
                uint32_t koff = (uint32_t)(s * 16) * 2;
                uint32_t ah[4], al[4], bh[4], bl[4];
                LDSM_X4(ah, a_base_h + a_lane + koff);
                LDSM_X4(al, a_base_l + a_lane + koff);
                LDSM_X4(bh, b_base_h + koff);
                LDSM_X4(bl, b_base_l + koff);
                MMA16816(d[0], ah, bh[0], bh[1]);
                MMA16816(d[1], ah, bl[0], bl[1]);
                MMA16816(d[2], al, bh[0], bh[1]);
                MMA16816(d[3], ah, bh[2], bh[3]);
                MMA16816(d[4], ah, bl[2], bl[3]);
                MMA16816(d[5], al, bh[2], bh[3]);
            }
            int m0 = lane >> 2, cc = 2 * (lane & 3);
            int r0 = wid * 16 + cc;
            int r1 = wid * 16 + 8 + cc;
            float e0[4], e1[4];
            #pragma unroll
            for (int e = 0; e < 4; ++e) {
                e0[e] = d[0][e] + d[1][e] + d[2][e];
                e1[e] = d[3][e] + d[4][e] + d[5][e];
            }
            a_sh[(r0 + 0) * 17 + m0]     = e0[0];
            a_sh[(r0 + 1) * 17 + m0]     = e0[1];
            a_sh[(r0 + 0) * 17 + m0 + 8] = e0[2];
            a_sh[(r0 + 1) * 17 + m0 + 8] = e0[3];
            a_sh[(r1 + 0) * 17 + m0]     = e1[0];
            a_sh[(r1 + 1) * 17 + m0]     = e1[1];
            a_sh[(r1 + 0) * 17 + m0 + 8] = e1[2];
            a_sh[(r1 + 1) * 17 + m0 + 8] = e1[3];
        }
        __syncthreads();

        // gate update: one (n, q) per thread
        {
            float av0 = a_sh[( 0 + q) * 17 + n] + xwv[0];
            float av1 = a_sh[(16 + q) * 17 + n] + xwv[1];
            float av2 = a_sh[(32 + q) * 17 + n] + xwv[2];
            float av3 = a_sh[(48 + q) * 17 + n] + xwv[3];
            float ig = sigf(av0), fg = sigf(av1), og = sigf(av2), gg = tanhf_fast(av3);
            float c  = fg * c_sh[tid] + ig * gg;
            float hh = og * tanhf_fast(c);
            c_sh[tid] = c;
            __nv_bfloat16 hi = __float2bfloat16(hh);
            float hif = __bfloat162float(hi);
            __nv_bfloat16 lo = __float2bfloat16(hh - hif);
            g_hpk2[(t & 1) ^ 1][n * HIDDEN + jglob] =
                ((uint32_t)*(uint16_t*)&hi << 16) | *(uint16_t*)&lo;
            g_hall[t * (NBATCH * HIDDEN) + n * HIDDEN + jglob] = hh;
            g_hb[t * (NBATCH * HIDDEN) + n * HIDDEN + jglob] = hi;
        }
        grid_barrier(t, 32);
    }
}

// ---------------- target logits ----------------
__global__ void __launch_bounds__(256) tgt_kernel(
    const int* __restrict__ captions, const float* __restrict__ bv)
{
    int wid = threadIdx.x >> 5, lane = threadIdx.x & 31;
    int r = blockIdx.x * 8 + wid;
    int tg = captions[(r & 15) * 257 + (r >> 4) + 1];
    const float* hr = &g_hall[r * HIDDEN];
    const __nv_bfloat16* wv = &g_wvb[(size_t)tg * HIDDEN];
    float s = 0.f;
    #pragma unroll
    for (int i = 0; i < 16; ++i) {
        int k = lane + i * 32;
        s = fmaf(hr[k], __bfloat162float(wv[k]), s);
    }
    #pragma unroll
    for (int o = 16; o > 0; o >>= 1) s += __shfl_xor_sync(0xffffffffu, s, o);
    if (lane == 0) g_lt[r] = s + bv[tg];
}

// ---------------- vocab: bf16 mma.sync + streaming exp-sum ----------------
#define V_A_STRIDE 520
#define V_B_OFF    133120
#define V_B_SZ     18432
#define V_B_STRIDE 72
#define V_RED_OFF  169984
#define V_SMEM     171008
extern __shared__ __align__(16) char dsm_v[];
__global__ void __launch_bounds__(256, 1) vocab_kernel() {
    __nv_bfloat16* As = (__nv_bfloat16*)dsm_v;
    const int tid = threadIdx.x, lane = tid & 31, wid = tid >> 5;
    const int wm = wid >> 1, wn = wid & 1;
    const int mblk = blockIdx.x >> 2, g = blockIdx.x & 3;
    const int gbase = g * GCOLS;

    {
        const uint4* src = (const uint4*)(g_hb + (size_t)(mblk * 128) * HIDDEN);
        for (int i = tid; i < 8192; i += 256) {
            int r = i >> 6, u = i & 63;
            *(uint4*)(As + r * V_A_STRIDE + u * 8) = src[i];
        }
    }
    __syncthreads();

    const uint32_t a_base = smem_to_u32(dsm_v);
    const uint32_t a_lane = (uint32_t)((lane & 15) * V_A_STRIDE + (lane >> 4) * 8) * 2;
    const int bq = lane >> 3;
    const uint32_t b_lane = (uint32_t)(((bq >> 1) * 8 + (lane & 7)) * V_B_STRIDE + (bq & 1) * 8) * 2;

    float rs[2][2] = {{0.f, 0.f}, {0.f, 0.f}};

    for (int tt = 0; tt < VTILES; ++tt) {
        const int nbase = gbase + tt * 128;
        float bb[16];
        {
            int cb = nbase + wn * 64 + (lane & 3) * 2;
            #pragma unroll
            for (int nt = 0; nt < 8; ++nt) {
                bb[nt * 2 + 0] = g_bv2[cb + nt * 8 + 0];
                bb[nt * 2 + 1] = g_bv2[cb + nt * 8 + 1];
            }
        }
        float d[2][8][4];
        #pragma unroll
        for (int mt = 0; mt < 2; ++mt)
            #pragma unroll
            for (int nt = 0; nt < 8; ++nt)
                #pragma unroll
                for (int e = 0; e < 4; ++e) d[mt][nt][e] = 0.f;

        uint4 ld[4];
        #pragma unroll
        for (int q = 0; q < 4; ++q) {
            int j = q * 256 + tid;
            int n = j >> 3, u = j & 7;
            ld[q] = *(const uint4*)(g_wvb + (size_t)(nbase + n) * HIDDEN + u * 8);
        }
        #pragma unroll
        for (int q = 0; q < 4; ++q) {
            int j = q * 256 + tid;
            int n = j >> 3, u = j & 7;
            *(uint4*)((__nv_bfloat16*)(dsm_v + V_B_OFF) + n * V_B_STRIDE + u * 8) = ld[q];
        }
        __syncthreads();

        for (int kc = 0; kc < 8; ++kc) {
            if (kc < 7) {
                #pragma unroll
                for (int q = 0; q < 4; ++q) {
                    int j = q * 256 + tid;
                    int n = j >> 3, u = j & 7;
                    ld[q] = *(const uint4*)(g_wvb + (size_t)(nbase + n) * HIDDEN + (kc + 1) * 64 + u * 8);
                }
            }
            const uint32_t b_base = smem_to_u32(dsm_v + V_B_OFF + (kc & 1) * V_B_SZ) + (uint32_t)(wn * 64 * V_B_STRIDE) * 2;
            #pragma unroll
            for (int k16 = 0; k16 < 4; ++k16) {
                uint32_t a[2][4];
                #pragma unroll
                for (int mt = 0; mt < 2; ++mt) {
                    uint32_t aaddr = a_base + a_lane +
                        (uint32_t)((wm * 32 + mt * 16) * V_A_STRIDE + kc * 64 + k16 * 16) * 2;
                    LDSM_X4(a[mt], aaddr);
                }
                #pragma unroll
                for (int np = 0; np < 4; ++np) {
                    uint32_t b[4];
                    uint32_t baddr = b_base + b_lane + (uint32_t)(np * 16 * V_B_STRIDE + k16 * 16) * 2;
                    LDSM_X4(b, baddr);
                    MMA16816(d[0][np * 2 + 0], a[0], b[0], b[1]);
                    MMA16816(d[0][np * 2 + 1], a[0], b[2], b[3]);
                    MMA16816(d[1][np * 2 + 0], a[1], b[0], b[1]);
                    MMA16816(d[1][np * 2 + 1], a[1], b[2], b[3]);
                }
            }
            if (kc < 7) {
                __nv_bfloat16* dst = (__nv_bfloat16*)(dsm_v + V_B_OFF + ((kc + 1) & 1) * V_B_SZ);
                #pragma unroll
                for (int q = 0; q < 4; ++q) {
                    int j = q * 256 + tid;
                    int n = j >> 3, u = j & 7;
                    *(uint4*)(dst + n * V_B_STRIDE + u * 8) = ld[q];
                }
            }
            __syncthreads();
        }

        if (!(tt == VTILES - 1 && wn == 1)) {
            #pragma unroll
            for (int mt = 0; mt < 2; ++mt)
                #pragma unroll
                for (int rh = 0; rh < 2; ++rh) {
                    float s = 0.f;
                    #pragma unroll
                    for (int nt = 0; nt < 8; ++nt) {
                        s += exp2_fast(fmaf(d[mt][nt][rh * 2 + 0], LOG2E, bb[nt * 2 + 0]));
                        s += exp2_fast(fmaf(d[mt][nt][rh * 2 + 1], LOG2E, bb[nt * 2 + 1]));
                    }
                    rs[mt][rh] += s;
                }
        }
    }

    float* red = (float*)(dsm_v + V_RED_OFF);
    #pragma unroll
    for (int mt = 0; mt < 2; ++mt)
        #pragma unroll
        for (int rh = 0; rh < 2; ++rh) {
            float v = rs[mt][rh];
            v += __shfl_xor_sync(0xffffffffu, v, 1);
            v += __shfl_xor_sync(0xffffffffu, v, 2);
            if ((lane & 3) == 0) {
                int row = wm * 32 + mt * 16 + rh * 8 + (lane >> 2);
                red[row * 2 + wn] = v;
            }
        }
    __syncthreads();
    if (tid < 128) {
        g_ps[g * MROWS + mblk * 128 + tid] = red[tid * 2 + 0] + red[tid * 2 + 1];
    }
}

// ---------------- combine ----------------
__global__ void __launch_bounds__(1024) combine_kernel(
    const int* __restrict__ captions, float* __restrict__ out)
{
    __shared__ float sh[1024];
    int tid = threadIdx.x;
    float local = 0.f;
    for (int r = tid; r < MROWS; r += 1024) {
        float S = g_ps[r] + g_ps[MROWS + r] + g_ps[2 * MROWS + r] + g_ps[3 * MROWS + r];
        int tg = captions[(r & 15) * 257 + (r >> 4) + 1];
        if (tg != 0) local += logf(S) - g_lt[r];
    }
    sh[tid] = local;
    __syncthreads();
    for (int o = 512; o > 0; o >>= 1) {
        if (tid < o) sh[tid] += sh[tid + o];
        __syncthreads();
    }
    if (tid == 0) out[0] = sh[0] * (1.f / NBATCH);
}

// ---------------- launch ----------------
extern "C" void kernel_launch(void* const* d_in, const int* in_sizes, int n_in,
                              void* d_out, int out_size) {
    const int*   captions = (const int*)d_in[0];
    const float* W_embed  = (const float*)d_in[1];
    const float* Wx       = (const float*)d_in[2];
    const float* Wh       = (const float*)d_in[3];
    const float* b        = (const float*)d_in[4];
    const float* W_vocab  = (const float*)d_in[5];
    const float* b_vocab  = (const float*)d_in[6];
    const float* h_init   = (const float*)d_in[7];

    cudaFuncSetAttribute(lstm_kernel,      cudaFuncAttributeMaxDynamicSharedMemorySize, L_SMEM);
    cudaFuncSetAttribute(vocab_kernel,     cudaFuncAttributeMaxDynamicSharedMemorySize, V_SMEM);
    cudaFuncSetAttribute(embed_mma_kernel, cudaFuncAttributeMaxDynamicSharedMemorySize, E_SMEM);

    init_kernel<<<32, 256>>>(h_init, b_vocab);
    gather_x_kernel<<<256, 256>>>(captions, W_embed);
    conv_wx_kernel<<<dim3(G4 / 32, WORDVEC / 32), 256>>>(Wx);
    conv_wv_kernel<<<dim3(VOCABSZ / 32, HIDDEN / 32), 256>>>(W_vocab);
    embed_mma_kernel<<<512, 256, E_SMEM>>>(b);
    lstm_kernel<<<32, 256, L_SMEM>>>(Wh);
    tgt_kernel<<<512, 256>>>(captions, b_vocab);
    vocab_kernel<<<128, 256, V_SMEM>>>();
    combine_kernel<<<1, 1024>>>(captions, (float*)d_out);
}

// round 13
// speedup vs baseline: 2.0355x; 1.0340x over previous
#include <cuda_runtime.h>
#include <cuda_bf16.h>
#include <cstdint>
#include <math.h>

#define VOCABSZ 32000
#define VPAD    32128
#define WORDVEC 256
#define HIDDEN  512
#define TSTEPS  256
#define NBATCH  16
#define G4      2048
#define MROWS   4096
#define NTILN   251          // VPAD / 128
#define NJOBS   (32 * NTILN) // 8032
#define VCTAS   148
#define LOG2E   1.44269504f

// ---------------- device scratch ----------------
__device__ float          g_xw[TSTEPS * NBATCH * G4];
__device__ float          g_hall[MROWS * HIDDEN];          // [t][n][k] fp32
__device__ __nv_bfloat16  g_hb[MROWS * HIDDEN];            // bf16 copy (written by lstm)
__device__ __nv_bfloat16  g_wvb[(size_t)VPAD * HIDDEN];    // Wv^T bf16 [v][k]
__device__ __nv_bfloat16  g_xb[MROWS * WORDVEC];           // gathered embeddings bf16
__device__ __nv_bfloat16  g_wxT[G4 * WORDVEC];             // Wx^T bf16
__device__ float          g_bv2[VPAD];                     // bv * LOG2E (pad = -120)
__device__ uint32_t       g_hpk2[2][NBATCH * HIDDEN];      // packed (hi,lo) bf16 h state
__device__ unsigned       g_barc[TSTEPS];
__device__ float          g_ps_flat[MROWS];                // per-row exp-sums (atomic)
__device__ float          g_lt[MROWS];

// ---------------- helpers ----------------
__device__ __forceinline__ float sigf(float x) { return __fdividef(1.f, 1.f + __expf(-x)); }
__device__ __forceinline__ float tanhf_fast(float x) { return __fdividef(2.f, 1.f + __expf(-2.f * x)) - 1.f; }
__device__ __forceinline__ uint32_t smem_to_u32(const void* p) {
    uint32_t a;
    asm("{ .reg .u64 t; cvta.to.shared.u64 t, %1; cvt.u32.u64 %0, t; }" : "=r"(a) : "l"(p));
    return a;
}
#define LDSM_X4(r, addr) asm volatile( \
    "ldmatrix.sync.aligned.m8n8.x4.shared.b16 {%0,%1,%2,%3}, [%4];" \
    : "=r"((r)[0]), "=r"((r)[1]), "=r"((r)[2]), "=r"((r)[3]) : "r"(addr))
#define MMA16816(d, a, b0, b1) asm volatile( \
    "mma.sync.aligned.m16n8k16.row.col.f32.bf16.bf16.f32 " \
    "{%0,%1,%2,%3}, {%4,%5,%6,%7}, {%8,%9}, {%0,%1,%2,%3};" \
    : "+f"((d)[0]), "+f"((d)[1]), "+f"((d)[2]), "+f"((d)[3]) \
    : "r"((a)[0]), "r"((a)[1]), "r"((a)[2]), "r"((a)[3]), "r"(b0), "r"(b1))

__device__ __forceinline__ float exp2_fast(float t) {
    int i = __float2int_rn(t);
    float f = t - (float)i;
    float p = fmaf(f, 0.00133335581f, 0.00961812911f);
    p = fmaf(f, p, 0.0555041087f);
    p = fmaf(f, p, 0.240226507f);
    p = fmaf(f, p, 0.693147181f);
    p = fmaf(f, p, 1.0f);
    return __int_as_float(__float_as_int(p) + (i << 23));
}

__device__ __forceinline__ void grid_barrier(int idx, unsigned nblocks) {
    __threadfence();
    __syncthreads();
    if (threadIdx.x == 0) {
        atomicAdd(&g_barc[idx], 1u);
        volatile unsigned* p = &g_barc[idx];
        while (*p < nblocks) { }
        __threadfence();
    }
    __syncthreads();
}

// ---------------- init (every replay) ----------------
__global__ void __launch_bounds__(256) init_kernel(
    const float* __restrict__ h_init, const float* __restrict__ bv)
{
    int gid = blockIdx.x * 256 + threadIdx.x;            // 8192 threads
    if (gid < TSTEPS) g_barc[gid] = 0u;
    if (gid < MROWS) g_ps_flat[gid] = 0.f;
    if (gid < NBATCH * HIDDEN) {
        int k = gid & 511;
        float v = h_init[k];
        __nv_bfloat16 hi = __float2bfloat16(v);
        float hif = __bfloat162float(hi);
        __nv_bfloat16 lo = __float2bfloat16(v - hif);
        g_hpk2[0][gid] = ((uint32_t)*(uint16_t*)&hi << 16) | *(uint16_t*)&lo;
    }
    for (int j = gid; j < (VPAD - VOCABSZ) * HIDDEN; j += 8192)
        g_wvb[(size_t)VOCABSZ * HIDDEN + j] = __float2bfloat16(0.f);
    for (int j = gid; j < VPAD; j += 8192)
        g_bv2[j] = (j < VOCABSZ) ? bv[j] * LOG2E : -120.f;
}

// ---------------- prep: gather embeddings + Wx transpose (fused) ----------------
__global__ void __launch_bounds__(256) prep_kernel(
    const int* __restrict__ captions, const float* __restrict__ W_embed,
    const float* __restrict__ Wx)
{
    __shared__ float sh[32 * 33];
    if (blockIdx.x < 256) {
        // gather embeddings -> bf16
        int gid = blockIdx.x * 256 + threadIdx.x;
        int idx = gid * 4;
        int r = idx >> 8, d = idx & 255;
        int tok = captions[(r & 15) * 257 + (r >> 4)];
        float4 v = *(const float4*)&W_embed[tok * WORDVEC + d];
        __nv_bfloat16 o[4];
        o[0] = __float2bfloat16(v.x); o[1] = __float2bfloat16(v.y);
        o[2] = __float2bfloat16(v.z); o[3] = __float2bfloat16(v.w);
        *(uint2*)&g_xb[idx] = *(const uint2*)o;
    } else {
        // Wx transpose + bf16: [256][2048] -> [2048][256]
        int bid2 = blockIdx.x - 256;
        int n0 = (bid2 & 63) * 32, k0 = (bid2 >> 6) * 32;
        int tx = threadIdx.x & 31, ty = threadIdx.x >> 5;
        #pragma unroll
        for (int i = 0; i < 4; ++i) {
            int k = ty + i * 8;
            sh[k * 33 + tx] = Wx[(k0 + k) * G4 + n0 + tx];
        }
        __syncthreads();
        #pragma unroll
        for (int i = 0; i < 4; ++i) {
            int n = ty + i * 8;
            g_wxT[(n0 + n) * WORDVEC + k0 + tx] = __float2bfloat16(sh[tx * 33 + n]);
        }
    }
}

// ---------------- Wv transpose + bf16 ----------------
__global__ void __launch_bounds__(256) conv_wv_kernel(const float* __restrict__ Wv) {
    __shared__ float sh[32 * 33];
    int n0 = blockIdx.x * 32, k0 = blockIdx.y * 32;
    int tx = threadIdx.x & 31, ty = threadIdx.x >> 5;
    #pragma unroll
    for (int i = 0; i < 4; ++i) {
        int k = ty + i * 8;
        sh[k * 33 + tx] = Wv[(size_t)(k0 + k) * VOCABSZ + n0 + tx];
    }
    __syncthreads();
    #pragma unroll
    for (int i = 0; i < 4; ++i) {
        int n = ty + i * 8;
        g_wvb[(size_t)(n0 + n) * HIDDEN + k0 + tx] = __float2bfloat16(sh[tx * 33 + n]);
    }
}

// ---------------- embed GEMM (bf16 mma.sync) ----------------
#define E_A_STRIDE 264
#define E_B_OFF    67584
#define E_SMEM     135168
extern __shared__ __align__(16) char dsm_e[];
__global__ void __launch_bounds__(256, 1) embed_mma_kernel(const float* __restrict__ b) {
    __nv_bfloat16* As = (__nv_bfloat16*)dsm_e;
    __nv_bfloat16* Bs = (__nv_bfloat16*)(dsm_e + E_B_OFF);
    const int tid = threadIdx.x, lane = tid & 31, wid = tid >> 5;
    const int wm = wid >> 1, wn = wid & 1;
    const int mblk = blockIdx.x >> 4, nblk = blockIdx.x & 15;

    const uint4* asrc = (const uint4*)(g_xb + mblk * 128 * WORDVEC);
    const uint4* bsrc = (const uint4*)(g_wxT + nblk * 128 * WORDVEC);
    #pragma unroll
    for (int q = 0; q < 16; ++q) {
        int i = q * 256 + tid;
        int r = i >> 5, u = i & 31;
        *(uint4*)(As + r * E_A_STRIDE + u * 8) = asrc[i];
        *(uint4*)(Bs + r * E_A_STRIDE + u * 8) = bsrc[i];
    }
    __syncthreads();

    const uint32_t a_base = smem_to_u32(As);
    const uint32_t a_lane = (uint32_t)((lane & 15) * E_A_STRIDE + (lane >> 4) * 8) * 2;
    const int bq = lane >> 3;
    const uint32_t b_lane = (uint32_t)(((bq >> 1) * 8 + (lane & 7)) * E_A_STRIDE + (bq & 1) * 8) * 2;
    const uint32_t b_base = smem_to_u32(Bs) + (uint32_t)(wn * 64 * E_A_STRIDE) * 2;

    float d[2][8][4];
    #pragma unroll
    for (int mt = 0; mt < 2; ++mt)
        #pragma unroll
        for (int nt = 0; nt < 8; ++nt)
            #pragma unroll
            for (int e = 0; e < 4; ++e) d[mt][nt][e] = 0.f;

    #pragma unroll
    for (int k16 = 0; k16 < 16; ++k16) {
        const uint32_t koff = (uint32_t)(k16 * 16) * 2;
        uint32_t a[2][4];
        #pragma unroll
        for (int mt = 0; mt < 2; ++mt) {
            LDSM_X4(a[mt], a_base + a_lane + (uint32_t)((wm * 32 + mt * 16) * E_A_STRIDE) * 2 + koff);
        }
        #pragma unroll
        for (int np = 0; np < 4; ++np) {
            uint32_t bb[4];
            LDSM_X4(bb, b_base + b_lane + (uint32_t)(np * 16 * E_A_STRIDE) * 2 + koff);
            MMA16816(d[0][np * 2 + 0], a[0], bb[0], bb[1]);
            MMA16816(d[0][np * 2 + 1], a[0], bb[2], bb[3]);
            MMA16816(d[1][np * 2 + 0], a[1], bb[0], bb[1]);
            MMA16816(d[1][np * 2 + 1], a[1], bb[2], bb[3]);
        }
    }

    const int cbase = nblk * 128 + wn * 64 + (lane & 3) * 2;
    #pragma unroll
    for (int mt = 0; mt < 2; ++mt)
        #pragma unroll
        for (int rh = 0; rh < 2; ++rh) {
            int row = mblk * 128 + wm * 32 + mt * 16 + rh * 8 + (lane >> 2);
            #pragma unroll
            for (int nt = 0; nt < 8; ++nt) {
                int c = cbase + nt * 8;
                float2 v;
                v.x = d[mt][nt][rh * 2 + 0] + b[c];
                v.y = d[mt][nt][rh * 2 + 1] + b[c + 1];
                *(float2*)&g_xw[(size_t)row * G4 + c] = v;
            }
        }
}

// ---------------- persistent LSTM v2: tensor-core h@Wh via hi/lo bf16 split ------------
#define L_BH   0
#define L_BL   66560
#define L_AH   133120
#define L_AL   149760
#define L_ASH  166400
#define L_CSH  170752
#define L_SMEM 171776
extern __shared__ __align__(16) char dsm_l[];
__global__ void __launch_bounds__(256, 1) lstm_kernel(const float* __restrict__ Wh) {
    const int bid = blockIdx.x, tid = threadIdx.x;
    const int lane = tid & 31, wid = tid >> 5;
    uint16_t* Bh = (uint16_t*)(dsm_l + L_BH);
    uint16_t* Bl = (uint16_t*)(dsm_l + L_BL);
    uint16_t* Ah = (uint16_t*)(dsm_l + L_AH);
    uint16_t* Al = (uint16_t*)(dsm_l + L_AL);
    float* a_sh = (float*)(dsm_l + L_ASH);   // [64 rows][17]
    float* c_sh = (float*)(dsm_l + L_CSH);   // [256]

    for (int i = tid; i < 64 * 512; i += 256) {
        int k = i >> 6, r = i & 63;
        int jcol = (r >> 4) * 512 + bid * 16 + (r & 15);
        float w = Wh[k * G4 + jcol];
        __nv_bfloat16 hi = __float2bfloat16(w);
        float hif = __bfloat162float(hi);
        __nv_bfloat16 lo = __float2bfloat16(w - hif);
        Bh[r * 520 + k] = *(uint16_t*)&hi;
        Bl[r * 520 + k] = *(uint16_t*)&lo;
    }
    c_sh[tid] = 0.f;

    const int q = tid & 15, n = tid >> 4;
    const int jglob = bid * 16 + q;

    const uint32_t a_base_h = smem_to_u32(dsm_l + L_AH);
    const uint32_t a_base_l = smem_to_u32(dsm_l + L_AL);
    const uint32_t a_lane = (uint32_t)((lane & 15) * 520 + (lane >> 4) * 8) * 2;
    const int bq = lane >> 3;
    const uint32_t b_lane = (uint32_t)((wid * 16 + (bq >> 1) * 8 + (lane & 7)) * 520 + (bq & 1) * 8) * 2;
    const uint32_t b_base_h = smem_to_u32(dsm_l + L_BH) + b_lane;
    const uint32_t b_base_l = smem_to_u32(dsm_l + L_BL) + b_lane;

    for (int t = 0; t < TSTEPS; ++t) {
        const uint32_t* src = (const uint32_t*)g_hpk2[t & 1];
        #pragma unroll
        for (int j = 0; j < 32; ++j) {
            int idx = tid + j * 256;
            int an = idx >> 9, ak = idx & 511;
            uint32_t u = __ldcg(&src[idx]);
            Ah[an * 520 + ak] = (uint16_t)(u >> 16);
            Al[an * 520 + ak] = (uint16_t)(u & 0xffffu);
        }
        float xwv[4];
        #pragma unroll
        for (int g = 0; g < 4; ++g)
            xwv[g] = g_xw[(size_t)(t * NBATCH + n) * G4 + g * 512 + jglob];
        __syncthreads();

        if (wid < 4) {
            float d[6][4];
            #pragma unroll
            for (int i = 0; i < 6; ++i)
                #pragma unroll
                for (int e = 0; e < 4; ++e) d[i][e] = 0.f;

            #pragma unroll 8
            for (int s = 0; s < 32; ++s) {
                uint32_t koff = (uint32_t)(s * 16) * 2;
                uint32_t ah[4], al[4], bh[4], bl[4];
                LDSM_X4(ah, a_base_h + a_lane + koff);
                LDSM_X4(al, a_base_l + a_lane + koff);
                LDSM_X4(bh, b_base_h + koff);
                LDSM_X4(bl, b_base_l + koff);
                MMA16816(d[0], ah, bh[0], bh[1]);
                MMA16816(d[1], ah, bl[0], bl[1]);
                MMA16816(d[2], al, bh[0], bh[1]);
                MMA16816(d[3], ah, bh[2], bh[3]);
                MMA16816(d[4], ah, bl[2], bl[3]);
                MMA16816(d[5], al, bh[2], bh[3]);
            }
            int m0 = lane >> 2, cc = 2 * (lane & 3);
            int r0 = wid * 16 + cc;
            int r1 = wid * 16 + 8 + cc;
            float e0[4], e1[4];
            #pragma unroll
            for (int e = 0; e < 4; ++e) {
                e0[e] = d[0][e] + d[1][e] + d[2][e];
                e1[e] = d[3][e] + d[4][e] + d[5][e];
            }
            a_sh[(r0 + 0) * 17 + m0]     = e0[0];
            a_sh[(r0 + 1) * 17 + m0]     = e0[1];
            a_sh[(r0 + 0) * 17 + m0 + 8] = e0[2];
            a_sh[(r0 + 1) * 17 + m0 + 8] = e0[3];
            a_sh[(r1 + 0) * 17 + m0]     = e1[0];
            a_sh[(r1 + 1) * 17 + m0]     = e1[1];
            a_sh[(r1 + 0) * 17 + m0 + 8] = e1[2];
            a_sh[(r1 + 1) * 17 + m0 + 8] = e1[3];
        }
        __syncthreads();

        {
            float av0 = a_sh[( 0 + q) * 17 + n] + xwv[0];
            float av1 = a_sh[(16 + q) * 17 + n] + xwv[1];
            float av2 = a_sh[(32 + q) * 17 + n] + xwv[2];
            float av3 = a_sh[(48 + q) * 17 + n] + xwv[3];
            float ig = sigf(av0), fg = sigf(av1), og = sigf(av2), gg = tanhf_fast(av3);
            float c  = fg * c_sh[tid] + ig * gg;
            float hh = og * tanhf_fast(c);
            c_sh[tid] = c;
            __nv_bfloat16 hi = __float2bfloat16(hh);
            float hif = __bfloat162float(hi);
            __nv_bfloat16 lo = __float2bfloat16(hh - hif);
            g_hpk2[(t & 1) ^ 1][n * HIDDEN + jglob] =
                ((uint32_t)*(uint16_t*)&hi << 16) | *(uint16_t*)&lo;
            g_hall[t * (NBATCH * HIDDEN) + n * HIDDEN + jglob] = hh;
            g_hb[t * (NBATCH * HIDDEN) + n * HIDDEN + jglob] = hi;
        }
        grid_barrier(t, 32);
    }
}

// ---------------- target logits ----------------
__global__ void __launch_bounds__(256) tgt_kernel(
    const int* __restrict__ captions, const float* __restrict__ bv)
{
    int wid = threadIdx.x >> 5, lane = threadIdx.x & 31;
    int r = blockIdx.x * 8 + wid;
    int tg = captions[(r & 15) * 257 + (r >> 4) + 1];
    const float* hr = &g_hall[r * HIDDEN];
    const __nv_bfloat16* wv = &g_wvb[(size_t)tg * HIDDEN];
    float s = 0.f;
    #pragma unroll
    for (int i = 0; i < 16; ++i) {
        int k = lane + i * 32;
        s = fmaf(hr[k], __bfloat162float(wv[k]), s);
    }
    #pragma unroll
    for (int o = 16; o > 0; o >>= 1) s += __shfl_xor_sync(0xffffffffu, s, o);
    if (lane == 0) g_lt[r] = s + bv[tg];
}

// ---------------- vocab v3: flat jobs over 148 CTAs, bf16 mma + streaming exp-sum -----
#define V_A_STRIDE 520
#define V_B_OFF    133120
#define V_B_SZ     18432
#define V_B_STRIDE 72
#define V_RED_OFF  169984
#define V_SMEM     171008
extern __shared__ __align__(16) char dsm_v[];
__global__ void __launch_bounds__(256, 1) vocab_kernel() {
    __nv_bfloat16* As = (__nv_bfloat16*)dsm_v;
    float* red = (float*)(dsm_v + V_RED_OFF);
    const int tid = threadIdx.x, lane = tid & 31, wid = tid >> 5;
    const int wm = wid >> 1, wn = wid & 1;

    const int start = (int)(((long long)blockIdx.x * NJOBS) / VCTAS);
    const int end   = (int)(((long long)(blockIdx.x + 1) * NJOBS) / VCTAS);

    const uint32_t a_base = smem_to_u32(dsm_v);
    const uint32_t a_lane = (uint32_t)((lane & 15) * V_A_STRIDE + (lane >> 4) * 8) * 2;
    const int bq = lane >> 3;
    const uint32_t b_lane = (uint32_t)(((bq >> 1) * 8 + (lane & 7)) * V_B_STRIDE + (bq & 1) * 8) * 2;

    float rs[2][2] = {{0.f, 0.f}, {0.f, 0.f}};
    int cur_mblk = -1;

    for (int j = start; j < end; ++j) {
        const int mblk = j / NTILN, nt = j % NTILN;

        if (mblk != cur_mblk) {
            // flush previous mblk partials
            if (cur_mblk >= 0) {
                #pragma unroll
                for (int mt = 0; mt < 2; ++mt)
                    #pragma unroll
                    for (int rh = 0; rh < 2; ++rh) {
                        float v = rs[mt][rh];
                        v += __shfl_xor_sync(0xffffffffu, v, 1);
                        v += __shfl_xor_sync(0xffffffffu, v, 2);
                        if ((lane & 3) == 0)
                            red[(wm * 32 + mt * 16 + rh * 8 + (lane >> 2)) * 2 + wn] = v;
                        rs[mt][rh] = 0.f;
                    }
                __syncthreads();
                if (tid < 128)
                    atomicAdd(&g_ps_flat[cur_mblk * 128 + tid], red[tid * 2] + red[tid * 2 + 1]);
            }
            // load A tile for new mblk
            __syncthreads();
            const uint4* src = (const uint4*)(g_hb + (size_t)(mblk * 128) * HIDDEN);
            for (int i = tid; i < 8192; i += 256) {
                int r = i >> 6, u = i & 63;
                *(uint4*)(As + r * V_A_STRIDE + u * 8) = src[i];
            }
            __syncthreads();
            cur_mblk = mblk;
        }

        const int nbase = nt * 128;
        float bb[16];
        {
            int cb = nbase + wn * 64 + (lane & 3) * 2;
            #pragma unroll
            for (int nt2 = 0; nt2 < 8; ++nt2) {
                bb[nt2 * 2 + 0] = g_bv2[cb + nt2 * 8 + 0];
                bb[nt2 * 2 + 1] = g_bv2[cb + nt2 * 8 + 1];
            }
        }
        float d[2][8][4];
        #pragma unroll
        for (int mt = 0; mt < 2; ++mt)
            #pragma unroll
            for (int nt2 = 0; nt2 < 8; ++nt2)
                #pragma unroll
                for (int e = 0; e < 4; ++e) d[mt][nt2][e] = 0.f;

        uint4 ld[4];
        #pragma unroll
        for (int qq = 0; qq < 4; ++qq) {
            int i = qq * 256 + tid;
            int n = i >> 3, u = i & 7;
            ld[qq] = *(const uint4*)(g_wvb + (size_t)(nbase + n) * HIDDEN + u * 8);
        }
        #pragma unroll
        for (int qq = 0; qq < 4; ++qq) {
            int i = qq * 256 + tid;
            int n = i >> 3, u = i & 7;
            *(uint4*)((__nv_bfloat16*)(dsm_v + V_B_OFF) + n * V_B_STRIDE + u * 8) = ld[qq];
        }
        __syncthreads();

        for (int kc = 0; kc < 8; ++kc) {
            if (kc < 7) {
                #pragma unroll
                for (int qq = 0; qq < 4; ++qq) {
                    int i = qq * 256 + tid;
                    int n = i >> 3, u = i & 7;
                    ld[qq] = *(const uint4*)(g_wvb + (size_t)(nbase + n) * HIDDEN + (kc + 1) * 64 + u * 8);
                }
            }
            const uint32_t b_base = smem_to_u32(dsm_v + V_B_OFF + (kc & 1) * V_B_SZ) + (uint32_t)(wn * 64 * V_B_STRIDE) * 2;
            #pragma unroll
            for (int k16 = 0; k16 < 4; ++k16) {
                uint32_t a[2][4];
                #pragma unroll
                for (int mt = 0; mt < 2; ++mt) {
                    uint32_t aaddr = a_base + a_lane +
                        (uint32_t)((wm * 32 + mt * 16) * V_A_STRIDE + kc * 64 + k16 * 16) * 2;
                    LDSM_X4(a[mt], aaddr);
                }
                #pragma unroll
                for (int np = 0; np < 4; ++np) {
                    uint32_t b[4];
                    uint32_t baddr = b_base + b_lane + (uint32_t)(np * 16 * V_B_STRIDE + k16 * 16) * 2;
                    LDSM_X4(b, baddr);
                    MMA16816(d[0][np * 2 + 0], a[0], b[0], b[1]);
                    MMA16816(d[0][np * 2 + 1], a[0], b[2], b[3]);
                    MMA16816(d[1][np * 2 + 0], a[1], b[0], b[1]);
                    MMA16816(d[1][np * 2 + 1], a[1], b[2], b[3]);
                }
            }
            if (kc < 7) {
                __nv_bfloat16* dst = (__nv_bfloat16*)(dsm_v + V_B_OFF + ((kc + 1) & 1) * V_B_SZ);
                #pragma unroll
                for (int qq = 0; qq < 4; ++qq) {
                    int i = qq * 256 + tid;
                    int n = i >> 3, u = i & 7;
                    *(uint4*)(dst + n * V_B_STRIDE + u * 8) = ld[qq];
                }
            }
            __syncthreads();
        }

        #pragma unroll
        for (int mt = 0; mt < 2; ++mt)
            #pragma unroll
            for (int rh = 0; rh < 2; ++rh) {
                float s = 0.f;
                #pragma unroll
                for (int nt2 = 0; nt2 < 8; ++nt2) {
                    s += exp2_fast(fmaf(d[mt][nt2][rh * 2 + 0], LOG2E, bb[nt2 * 2 + 0]));
                    s += exp2_fast(fmaf(d[mt][nt2][rh * 2 + 1], LOG2E, bb[nt2 * 2 + 1]));
                }
                rs[mt][rh] += s;
            }
    }

    // final flush
    if (cur_mblk >= 0) {
        #pragma unroll
        for (int mt = 0; mt < 2; ++mt)
            #pragma unroll
            for (int rh = 0; rh < 2; ++rh) {
                float v = rs[mt][rh];
                v += __shfl_xor_sync(0xffffffffu, v, 1);
                v += __shfl_xor_sync(0xffffffffu, v, 2);
                if ((lane & 3) == 0)
                    red[(wm * 32 + mt * 16 + rh * 8 + (lane >> 2)) * 2 + wn] = v;
            }
        __syncthreads();
        if (tid < 128)
            atomicAdd(&g_ps_flat[cur_mblk * 128 + tid], red[tid * 2] + red[tid * 2 + 1]);
    }
}

// ---------------- combine ----------------
__global__ void __launch_bounds__(1024) combine_kernel(
    const int* __restrict__ captions, float* __restrict__ out)
{
    __shared__ float sh[1024];
    int tid = threadIdx.x;
    float local = 0.f;
    for (int r = tid; r < MROWS; r += 1024) {
        float S = g_ps_flat[r];
        int tg = captions[(r & 15) * 257 + (r >> 4) + 1];
        if (tg != 0) local += logf(S) - g_lt[r];
    }
    sh[tid] = local;
    __syncthreads();
    for (int o = 512; o > 0; o >>= 1) {
        if (tid < o) sh[tid] += sh[tid + o];
        __syncthreads();
    }
    if (tid == 0) out[0] = sh[0] * (1.f / NBATCH);
}

// ---------------- launch ----------------
extern "C" void kernel_launch(void* const* d_in, const int* in_sizes, int n_in,
                              void* d_out, int out_size) {
    const int*   captions = (const int*)d_in[0];
    const float* W_embed  = (const float*)d_in[1];
    const float* Wx       = (const float*)d_in[2];
    const float* Wh       = (const float*)d_in[3];
    const float* b        = (const float*)d_in[4];
    const float* W_vocab  = (const float*)d_in[5];
    const float* b_vocab  = (const float*)d_in[6];
    const float* h_init   = (const float*)d_in[7];

    cudaFuncSetAttribute(lstm_kernel,      cudaFuncAttributeMaxDynamicSharedMemorySize, L_SMEM);
    cudaFuncSetAttribute(vocab_kernel,     cudaFuncAttributeMaxDynamicSharedMemorySize, V_SMEM);
    cudaFuncSetAttribute(embed_mma_kernel, cudaFuncAttributeMaxDynamicSharedMemorySize, E_SMEM);

    init_kernel<<<32, 256>>>(h_init, b_vocab);
    prep_kernel<<<768, 256>>>(captions, W_embed, Wx);
    embed_mma_kernel<<<512, 256, E_SMEM>>>(b);
    lstm_kernel<<<32, 256, L_SMEM>>>(Wh);                      // 4th launch -> profiled
    conv_wv_kernel<<<dim3(VOCABSZ / 32, HIDDEN / 32), 256>>>(W_vocab);
    tgt_kernel<<<512, 256>>>(captions, b_vocab);
    vocab_kernel<<<VCTAS, 256, V_SMEM>>>();
    combine_kernel<<<1, 1024>>>(captions, (float*)d_out);
}

// round 14
// speedup vs baseline: 2.1469x; 1.0548x over previous
#include <cuda_runtime.h>
#include <cuda_bf16.h>
#include <cstdint>
#include <math.h>

#define VOCABSZ 32000
#define VPAD    32128
#define WORDVEC 256
#define HIDDEN  512
#define TSTEPS  256
#define NBATCH  16
#define G4      2048
#define MROWS   4096
#define NTILN   251          // VPAD / 128
#define NJOBS   (32 * NTILN) // 8032
#define VCTAS   148
#define LOG2E   1.44269504f

// ---------------- device scratch ----------------
__device__ float          g_xw[TSTEPS * NBATCH * G4];
__device__ __nv_bfloat16  g_hb[MROWS * HIDDEN];            // bf16 h history (written by lstm)
__device__ __nv_bfloat16  g_wvb[(size_t)VPAD * HIDDEN];    // Wv^T bf16 [v][k]
__device__ __nv_bfloat16  g_xb[MROWS * WORDVEC];           // gathered embeddings bf16
__device__ __nv_bfloat16  g_wxT[G4 * WORDVEC];             // Wx^T bf16
__device__ float          g_bv2[VPAD];                     // bv * LOG2E (pad = -120)
__device__ uint32_t       g_hpk2[2][NBATCH * HIDDEN];      // packed (hi,lo) bf16 h state
__device__ unsigned       g_barc[TSTEPS];
__device__ float          g_ps_flat[MROWS];                // per-row exp-sums (atomic)
__device__ float          g_lt[MROWS];

// ---------------- helpers ----------------
__device__ __forceinline__ float sigf(float x) { return __fdividef(1.f, 1.f + __expf(-x)); }
__device__ __forceinline__ float tanhf_fast(float x) { return __fdividef(2.f, 1.f + __expf(-2.f * x)) - 1.f; }
__device__ __forceinline__ uint32_t smem_to_u32(const void* p) {
    uint32_t a;
    asm("{ .reg .u64 t; cvta.to.shared.u64 t, %1; cvt.u32.u64 %0, t; }" : "=r"(a) : "l"(p));
    return a;
}
__device__ __forceinline__ float bf16lo_f(uint32_t u) { return __uint_as_float(u << 16); }
__device__ __forceinline__ float bf16hi_f(uint32_t u) { return __uint_as_float(u & 0xffff0000u); }
#define LDSM_X4(r, addr) asm volatile( \
    "ldmatrix.sync.aligned.m8n8.x4.shared.b16 {%0,%1,%2,%3}, [%4];" \
    : "=r"((r)[0]), "=r"((r)[1]), "=r"((r)[2]), "=r"((r)[3]) : "r"(addr))
#define MMA16816(d, a, b0, b1) asm volatile( \
    "mma.sync.aligned.m16n8k16.row.col.f32.bf16.bf16.f32 " \
    "{%0,%1,%2,%3}, {%4,%5,%6,%7}, {%8,%9}, {%0,%1,%2,%3};" \
    : "+f"((d)[0]), "+f"((d)[1]), "+f"((d)[2]), "+f"((d)[3]) \
    : "r"((a)[0]), "r"((a)[1]), "r"((a)[2]), "r"((a)[3]), "r"(b0), "r"(b1))

__device__ __forceinline__ float exp2_fast(float t) {
    int i = __float2int_rn(t);
    float f = t - (float)i;
    float p = fmaf(f, 0.00133335581f, 0.00961812911f);
    p = fmaf(f, p, 0.0555041087f);
    p = fmaf(f, p, 0.240226507f);
    p = fmaf(f, p, 0.693147181f);
    p = fmaf(f, p, 1.0f);
    return __int_as_float(__float_as_int(p) + (i << 23));
}

__device__ __forceinline__ void grid_barrier(int idx, unsigned nblocks) {
    __threadfence();
    __syncthreads();
    if (threadIdx.x == 0) {
        atomicAdd(&g_barc[idx], 1u);
        volatile unsigned* p = &g_barc[idx];
        while (*p < nblocks) { }
        __threadfence();
    }
    __syncthreads();
}

// ---------------- init (every replay) ----------------
__global__ void __launch_bounds__(256) init_kernel(
    const float* __restrict__ h_init, const float* __restrict__ bv)
{
    int gid = blockIdx.x * 256 + threadIdx.x;            // 8192 threads
    if (gid < TSTEPS) g_barc[gid] = 0u;
    if (gid < MROWS) g_ps_flat[gid] = 0.f;
    if (gid < NBATCH * HIDDEN) {
        int k = gid & 511;
        float v = h_init[k];
        __nv_bfloat16 hi = __float2bfloat16(v);
        float hif = __bfloat162float(hi);
        __nv_bfloat16 lo = __float2bfloat16(v - hif);
        g_hpk2[0][gid] = ((uint32_t)*(uint16_t*)&hi << 16) | *(uint16_t*)&lo;
    }
    for (int j = gid; j < (VPAD - VOCABSZ) * HIDDEN; j += 8192)
        g_wvb[(size_t)VOCABSZ * HIDDEN + j] = __float2bfloat16(0.f);
    for (int j = gid; j < VPAD; j += 8192)
        g_bv2[j] = (j < VOCABSZ) ? bv[j] * LOG2E : -120.f;
}

// ---------------- prep: gather embeddings + Wx transpose (fused) ----------------
__global__ void __launch_bounds__(256) prep_kernel(
    const int* __restrict__ captions, const float* __restrict__ W_embed,
    const float* __restrict__ Wx)
{
    __shared__ float sh[32 * 33];
    if (blockIdx.x < 256) {
        int gid = blockIdx.x * 256 + threadIdx.x;
        int idx = gid * 4;
        int r = idx >> 8, d = idx & 255;
        int tok = captions[(r & 15) * 257 + (r >> 4)];
        float4 v = *(const float4*)&W_embed[tok * WORDVEC + d];
        __nv_bfloat16 o[4];
        o[0] = __float2bfloat16(v.x); o[1] = __float2bfloat16(v.y);
        o[2] = __float2bfloat16(v.z); o[3] = __float2bfloat16(v.w);
        *(uint2*)&g_xb[idx] = *(const uint2*)o;
    } else {
        int bid2 = blockIdx.x - 256;
        int n0 = (bid2 & 63) * 32, k0 = (bid2 >> 6) * 32;
        int tx = threadIdx.x & 31, ty = threadIdx.x >> 5;
        #pragma unroll
        for (int i = 0; i < 4; ++i) {
            int k = ty + i * 8;
            sh[k * 33 + tx] = Wx[(k0 + k) * G4 + n0 + tx];
        }
        __syncthreads();
        #pragma unroll
        for (int i = 0; i < 4; ++i) {
            int n = ty + i * 8;
            g_wxT[(n0 + n) * WORDVEC + k0 + tx] = __float2bfloat16(sh[tx * 33 + n]);
        }
    }
}

// ---------------- Wv transpose + bf16 ----------------
__global__ void __launch_bounds__(256) conv_wv_kernel(const float* __restrict__ Wv) {
    __shared__ float sh[32 * 33];
    int n0 = blockIdx.x * 32, k0 = blockIdx.y * 32;
    int tx = threadIdx.x & 31, ty = threadIdx.x >> 5;
    #pragma unroll
    for (int i = 0; i < 4; ++i) {
        int k = ty + i * 8;
        sh[k * 33 + tx] = Wv[(size_t)(k0 + k) * VOCABSZ + n0 + tx];
    }
    __syncthreads();
    #pragma unroll
    for (int i = 0; i < 4; ++i) {
        int n = ty + i * 8;
        g_wvb[(size_t)(n0 + n) * HIDDEN + k0 + tx] = __float2bfloat16(sh[tx * 33 + n]);
    }
}

// ---------------- embed GEMM (bf16 mma.sync) ----------------
#define E_A_STRIDE 264
#define E_B_OFF    67584
#define E_SMEM     135168
extern __shared__ __align__(16) char dsm_e[];
__global__ void __launch_bounds__(256, 1) embed_mma_kernel(const float* __restrict__ b) {
    __nv_bfloat16* As = (__nv_bfloat16*)dsm_e;
    __nv_bfloat16* Bs = (__nv_bfloat16*)(dsm_e + E_B_OFF);
    const int tid = threadIdx.x, lane = tid & 31, wid = tid >> 5;
    const int wm = wid >> 1, wn = wid & 1;
    const int mblk = blockIdx.x >> 4, nblk = blockIdx.x & 15;

    const uint4* asrc = (const uint4*)(g_xb + mblk * 128 * WORDVEC);
    const uint4* bsrc = (const uint4*)(g_wxT + nblk * 128 * WORDVEC);
    #pragma unroll
    for (int q = 0; q < 16; ++q) {
        int i = q * 256 + tid;
        int r = i >> 5, u = i & 31;
        *(uint4*)(As + r * E_A_STRIDE + u * 8) = asrc[i];
        *(uint4*)(Bs + r * E_A_STRIDE + u * 8) = bsrc[i];
    }
    __syncthreads();

    const uint32_t a_base = smem_to_u32(As);
    const uint32_t a_lane = (uint32_t)((lane & 15) * E_A_STRIDE + (lane >> 4) * 8) * 2;
    const int bq = lane >> 3;
    const uint32_t b_lane = (uint32_t)(((bq >> 1) * 8 + (lane & 7)) * E_A_STRIDE + (bq & 1) * 8) * 2;
    const uint32_t b_base = smem_to_u32(Bs) + (uint32_t)(wn * 64 * E_A_STRIDE) * 2;

    float d[2][8][4];
    #pragma unroll
    for (int mt = 0; mt < 2; ++mt)
        #pragma unroll
        for (int nt = 0; nt < 8; ++nt)
            #pragma unroll
            for (int e = 0; e < 4; ++e) d[mt][nt][e] = 0.f;

    #pragma unroll
    for (int k16 = 0; k16 < 16; ++k16) {
        const uint32_t koff = (uint32_t)(k16 * 16) * 2;
        uint32_t a[2][4];
        #pragma unroll
        for (int mt = 0; mt < 2; ++mt) {
            LDSM_X4(a[mt], a_base + a_lane + (uint32_t)((wm * 32 + mt * 16) * E_A_STRIDE) * 2 + koff);
        }
        #pragma unroll
        for (int np = 0; np < 4; ++np) {
            uint32_t bb[4];
            LDSM_X4(bb, b_base + b_lane + (uint32_t)(np * 16 * E_A_STRIDE) * 2 + koff);
            MMA16816(d[0][np * 2 + 0], a[0], bb[0], bb[1]);
            MMA16816(d[0][np * 2 + 1], a[0], bb[2], bb[3]);
            MMA16816(d[1][np * 2 + 0], a[1], bb[0], bb[1]);
            MMA16816(d[1][np * 2 + 1], a[1], bb[2], bb[3]);
        }
    }

    const int cbase = nblk * 128 + wn * 64 + (lane & 3) * 2;
    #pragma unroll
    for (int mt = 0; mt < 2; ++mt)
        #pragma unroll
        for (int rh = 0; rh < 2; ++rh) {
            int row = mblk * 128 + wm * 32 + mt * 16 + rh * 8 + (lane >> 2);
            #pragma unroll
            for (int nt = 0; nt < 8; ++nt) {
                int c = cbase + nt * 8;
                float2 v;
                v.x = d[mt][nt][rh * 2 + 0] + b[c];
                v.y = d[mt][nt][rh * 2 + 1] + b[c + 1];
                *(float2*)&g_xw[(size_t)row * G4 + c] = v;
            }
        }
}

// ---------------- persistent LSTM v3: tensor-core h@Wh, vectorized A-fill -------------
#define L_BH   0
#define L_BL   66560
#define L_AH   133120
#define L_AL   149760
#define L_ASH  166400
#define L_CSH  170752
#define L_SMEM 171776
extern __shared__ __align__(16) char dsm_l[];
__global__ void __launch_bounds__(256, 1) lstm_kernel(const float* __restrict__ Wh) {
    const int bid = blockIdx.x, tid = threadIdx.x;
    const int lane = tid & 31, wid = tid >> 5;
    uint16_t* Bh = (uint16_t*)(dsm_l + L_BH);
    uint16_t* Bl = (uint16_t*)(dsm_l + L_BL);
    uint16_t* Ah = (uint16_t*)(dsm_l + L_AH);
    uint16_t* Al = (uint16_t*)(dsm_l + L_AL);
    float* a_sh = (float*)(dsm_l + L_ASH);   // [64 rows][17]
    float* c_sh = (float*)(dsm_l + L_CSH);   // [256]

    for (int i = tid; i < 64 * 512; i += 256) {
        int k = i >> 6, r = i & 63;
        int jcol = (r >> 4) * 512 + bid * 16 + (r & 15);
        float w = Wh[k * G4 + jcol];
        __nv_bfloat16 hi = __float2bfloat16(w);
        float hif = __bfloat162float(hi);
        __nv_bfloat16 lo = __float2bfloat16(w - hif);
        Bh[r * 520 + k] = *(uint16_t*)&hi;
        Bl[r * 520 + k] = *(uint16_t*)&lo;
    }
    c_sh[tid] = 0.f;

    const int q = tid & 15, n = tid >> 4;
    const int jglob = bid * 16 + q;

    const uint32_t a_base_h = smem_to_u32(dsm_l + L_AH);
    const uint32_t a_base_l = smem_to_u32(dsm_l + L_AL);
    const uint32_t a_lane = (uint32_t)((lane & 15) * 520 + (lane >> 4) * 8) * 2;
    const int bq = lane >> 3;
    const uint32_t b_lane = (uint32_t)((wid * 16 + (bq >> 1) * 8 + (lane & 7)) * 520 + (bq & 1) * 8) * 2;
    const uint32_t b_base_h = smem_to_u32(dsm_l + L_BH) + b_lane;
    const uint32_t b_base_l = smem_to_u32(dsm_l + L_BL) + b_lane;

    for (int t = 0; t < TSTEPS; ++t) {
        // A fill: vectorized unpack of packed (hi,lo) h into two bf16 tiles [16][520]
        const uint4* src4 = (const uint4*)g_hpk2[t & 1];
        #pragma unroll
        for (int j = 0; j < 8; ++j) {
            int i4 = tid + j * 256;              // uint4 index, 2048 total
            int an = i4 >> 7;                    // (i4*4) >> 9
            int ak = (i4 << 2) & 511;
            uint4 u = __ldcg(&src4[i4]);
            uint32_t* ah32 = (uint32_t*)(Ah + an * 520 + ak);
            uint32_t* al32 = (uint32_t*)(Al + an * 520 + ak);
            ah32[0] = (u.y & 0xffff0000u) | (u.x >> 16);
            ah32[1] = (u.w & 0xffff0000u) | (u.z >> 16);
            al32[0] = (u.y << 16) | (u.x & 0xffffu);
            al32[1] = (u.w << 16) | (u.z & 0xffffu);
        }
        float xwv[4];
        #pragma unroll
        for (int g = 0; g < 4; ++g)
            xwv[g] = g_xw[(size_t)(t * NBATCH + n) * G4 + g * 512 + jglob];
        __syncthreads();

        if (wid < 4) {
            float d[6][4];
            #pragma unroll
            for (int i = 0; i < 6; ++i)
                #pragma unroll
                for (int e = 0; e < 4; ++e) d[i][e] = 0.f;

            #pragma unroll 8
            for (int s = 0; s < 32; ++s) {
                uint32_t koff = (uint32_t)(s * 16) * 2;
                uint32_t ah[4], al[4], bh[4], bl[4];
                LDSM_X4(ah, a_base_h + a_lane + koff);
                LDSM_X4(al, a_base_l + a_lane + koff);
                LDSM_X4(bh, b_base_h + koff);
                LDSM_X4(bl, b_base_l + koff);
                MMA16816(d[0], ah, bh[0], bh[1]);
                MMA16816(d[1], ah, bl[0], bl[1]);
                MMA16816(d[2], al, bh[0], bh[1]);
                MMA16816(d[3], ah, bh[2], bh[3]);
                MMA16816(d[4], ah, bl[2], bl[3]);
                MMA16816(d[5], al, bh[2], bh[3]);
            }
            int m0 = lane >> 2, cc = 2 * (lane & 3);
            int r0 = wid * 16 + cc;
            int r1 = wid * 16 + 8 + cc;
            float e0[4], e1[4];
            #pragma unroll
            for (int e = 0; e < 4; ++e) {
                e0[e] = d[0][e] + d[1][e] + d[2][e];
                e1[e] = d[3][e] + d[4][e] + d[5][e];
            }
            a_sh[(r0 + 0) * 17 + m0]     = e0[0];
            a_sh[(r0 + 1) * 17 + m0]     = e0[1];
            a_sh[(r0 + 0) * 17 + m0 + 8] = e0[2];
            a_sh[(r0 + 1) * 17 + m0 + 8] = e0[3];
            a_sh[(r1 + 0) * 17 + m0]     = e1[0];
            a_sh[(r1 + 1) * 17 + m0]     = e1[1];
            a_sh[(r1 + 0) * 17 + m0 + 8] = e1[2];
            a_sh[(r1 + 1) * 17 + m0 + 8] = e1[3];
        }
        __syncthreads();

        {
            float av0 = a_sh[( 0 + q) * 17 + n] + xwv[0];
            float av1 = a_sh[(16 + q) * 17 + n] + xwv[1];
            float av2 = a_sh[(32 + q) * 17 + n] + xwv[2];
            float av3 = a_sh[(48 + q) * 17 + n] + xwv[3];
            float ig = sigf(av0), fg = sigf(av1), og = sigf(av2), gg = tanhf_fast(av3);
            float c  = fg * c_sh[tid] + ig * gg;
            float hh = og * tanhf_fast(c);
            c_sh[tid] = c;
            __nv_bfloat16 hi = __float2bfloat16(hh);
            float hif = __bfloat162float(hi);
            __nv_bfloat16 lo = __float2bfloat16(hh - hif);
            g_hpk2[(t & 1) ^ 1][n * HIDDEN + jglob] =
                ((uint32_t)*(uint16_t*)&hi << 16) | *(uint16_t*)&lo;
            g_hb[t * (NBATCH * HIDDEN) + n * HIDDEN + jglob] = hi;
        }
        grid_barrier(t, 32);
    }
}

// ---------------- target logits (bf16 h, consistent with vocab GEMM) ----------------
__global__ void __launch_bounds__(256) tgt_kernel(
    const int* __restrict__ captions, const float* __restrict__ bv)
{
    int wid = threadIdx.x >> 5, lane = threadIdx.x & 31;
    int r = blockIdx.x * 8 + wid;
    int tg = captions[(r & 15) * 257 + (r >> 4) + 1];
    const uint4* hp4 = (const uint4*)(g_hb + (size_t)r * HIDDEN);
    const uint4* wp4 = (const uint4*)(g_wvb + (size_t)tg * HIDDEN);
    float s = 0.f;
    #pragma unroll
    for (int i = 0; i < 2; ++i) {
        uint4 hu = hp4[lane + i * 32];
        uint4 wu = wp4[lane + i * 32];
        s = fmaf(bf16lo_f(hu.x), bf16lo_f(wu.x), s);
        s = fmaf(bf16hi_f(hu.x), bf16hi_f(wu.x), s);
        s = fmaf(bf16lo_f(hu.y), bf16lo_f(wu.y), s);
        s = fmaf(bf16hi_f(hu.y), bf16hi_f(wu.y), s);
        s = fmaf(bf16lo_f(hu.z), bf16lo_f(wu.z), s);
        s = fmaf(bf16hi_f(hu.z), bf16hi_f(wu.z), s);
        s = fmaf(bf16lo_f(hu.w), bf16lo_f(wu.w), s);
        s = fmaf(bf16hi_f(hu.w), bf16hi_f(wu.w), s);
    }
    #pragma unroll
    for (int o = 16; o > 0; o >>= 1) s += __shfl_xor_sync(0xffffffffu, s, o);
    if (lane == 0) g_lt[r] = s + bv[tg];
}

// ---------------- vocab v3: flat jobs over 148 CTAs, bf16 mma + streaming exp-sum -----
#define V_A_STRIDE 520
#define V_B_OFF    133120
#define V_B_SZ     18432
#define V_B_STRIDE 72
#define V_RED_OFF  169984
#define V_SMEM     171008
extern __shared__ __align__(16) char dsm_v[];
__global__ void __launch_bounds__(256, 1) vocab_kernel() {
    __nv_bfloat16* As = (__nv_bfloat16*)dsm_v;
    float* red = (float*)(dsm_v + V_RED_OFF);
    const int tid = threadIdx.x, lane = tid & 31, wid = tid >> 5;
    const int wm = wid >> 1, wn = wid & 1;

    const int start = (int)(((long long)blockIdx.x * NJOBS) / VCTAS);
    const int end   = (int)(((long long)(blockIdx.x + 1) * NJOBS) / VCTAS);

    const uint32_t a_base = smem_to_u32(dsm_v);
    const uint32_t a_lane = (uint32_t)((lane & 15) * V_A_STRIDE + (lane >> 4) * 8) * 2;
    const int bq = lane >> 3;
    const uint32_t b_lane = (uint32_t)(((bq >> 1) * 8 + (lane & 7)) * V_B_STRIDE + (bq & 1) * 8) * 2;

    float rs[2][2] = {{0.f, 0.f}, {0.f, 0.f}};
    int cur_mblk = -1;

    for (int j = start; j < end; ++j) {
        const int mblk = j / NTILN, nt = j % NTILN;

        if (mblk != cur_mblk) {
            if (cur_mblk >= 0) {
                #pragma unroll
                for (int mt = 0; mt < 2; ++mt)
                    #pragma unroll
                    for (int rh = 0; rh < 2; ++rh) {
                        float v = rs[mt][rh];
                        v += __shfl_xor_sync(0xffffffffu, v, 1);
                        v += __shfl_xor_sync(0xffffffffu, v, 2);
                        if ((lane & 3) == 0)
                            red[(wm * 32 + mt * 16 + rh * 8 + (lane >> 2)) * 2 + wn] = v;
                        rs[mt][rh] = 0.f;
                    }
                __syncthreads();
                if (tid < 128)
                    atomicAdd(&g_ps_flat[cur_mblk * 128 + tid], red[tid * 2] + red[tid * 2 + 1]);
            }
            __syncthreads();
            const uint4* src = (const uint4*)(g_hb + (size_t)(mblk * 128) * HIDDEN);
            for (int i = tid; i < 8192; i += 256) {
                int r = i >> 6, u = i & 63;
                *(uint4*)(As + r * V_A_STRIDE + u * 8) = src[i];
            }
            __syncthreads();
            cur_mblk = mblk;
        }

        const int nbase = nt * 128;
        float bb[16];
        {
            int cb = nbase + wn * 64 + (lane & 3) * 2;
            #pragma unroll
            for (int nt2 = 0; nt2 < 8; ++nt2) {
                bb[nt2 * 2 + 0] = g_bv2[cb + nt2 * 8 + 0];
                bb[nt2 * 2 + 1] = g_bv2[cb + nt2 * 8 + 1];
            }
        }
        float d[2][8][4];
        #pragma unroll
        for (int mt = 0; mt < 2; ++mt)
            #pragma unroll
            for (int nt2 = 0; nt2 < 8; ++nt2)
                #pragma unroll
                for (int e = 0; e < 4; ++e) d[mt][nt2][e] = 0.f;

        uint4 ld[4];
        #pragma unroll
        for (int qq = 0; qq < 4; ++qq) {
            int i = qq * 256 + tid;
            int n = i >> 3, u = i & 7;
            ld[qq] = *(const uint4*)(g_wvb + (size_t)(nbase + n) * HIDDEN + u * 8);
        }
        #pragma unroll
        for (int qq = 0; qq < 4; ++qq) {
            int i = qq * 256 + tid;
            int n = i >> 3, u = i & 7;
            *(uint4*)((__nv_bfloat16*)(dsm_v + V_B_OFF) + n * V_B_STRIDE + u * 8) = ld[qq];
        }
        __syncthreads();

        for (int kc = 0; kc < 8; ++kc) {
            if (kc < 7) {
                #pragma unroll
                for (int qq = 0; qq < 4; ++qq) {
                    int i = qq * 256 + tid;
                    int n = i >> 3, u = i & 7;
                    ld[qq] = *(const uint4*)(g_wvb + (size_t)(nbase + n) * HIDDEN + (kc + 1) * 64 + u * 8);
                }
            }
            const uint32_t b_base = smem_to_u32(dsm_v + V_B_OFF + (kc & 1) * V_B_SZ) + (uint32_t)(wn * 64 * V_B_STRIDE) * 2;
            #pragma unroll
            for (int k16 = 0; k16 < 4; ++k16) {
                uint32_t a[2][4];
                #pragma unroll
                for (int mt = 0; mt < 2; ++mt) {
                    uint32_t aaddr = a_base + a_lane +
                        (uint32_t)((wm * 32 + mt * 16) * V_A_STRIDE + kc * 64 + k16 * 16) * 2;
                    LDSM_X4(a[mt], aaddr);
                }
                #pragma unroll
                for (int np = 0; np < 4; ++np) {
                    uint32_t b[4];
                    uint32_t baddr = b_base + b_lane + (uint32_t)(np * 16 * V_B_STRIDE + k16 * 16) * 2;
                    LDSM_X4(b, baddr);
                    MMA16816(d[0][np * 2 + 0], a[0], b[0], b[1]);
                    MMA16816(d[0][np * 2 + 1], a[0], b[2], b[3]);
                    MMA16816(d[1][np * 2 + 0], a[1], b[0], b[1]);
                    MMA16816(d[1][np * 2 + 1], a[1], b[2], b[3]);
                }
            }
            if (kc < 7) {
                __nv_bfloat16* dst = (__nv_bfloat16*)(dsm_v + V_B_OFF + ((kc + 1) & 1) * V_B_SZ);
                #pragma unroll
                for (int qq = 0; qq < 4; ++qq) {
                    int i = qq * 256 + tid;
                    int n = i >> 3, u = i & 7;
                    *(uint4*)(dst + n * V_B_STRIDE + u * 8) = ld[qq];
                }
            }
            __syncthreads();
        }

        #pragma unroll
        for (int mt = 0; mt < 2; ++mt)
            #pragma unroll
            for (int rh = 0; rh < 2; ++rh) {
                float s = 0.f;
                #pragma unroll
                for (int nt2 = 0; nt2 < 8; ++nt2) {
                    s += exp2_fast(fmaf(d[mt][nt2][rh * 2 + 0], LOG2E, bb[nt2 * 2 + 0]));
                    s += exp2_fast(fmaf(d[mt][nt2][rh * 2 + 1], LOG2E, bb[nt2 * 2 + 1]));
                }
                rs[mt][rh] += s;
            }
    }

    if (cur_mblk >= 0) {
        #pragma unroll
        for (int mt = 0; mt < 2; ++mt)
            #pragma unroll
            for (int rh = 0; rh < 2; ++rh) {
                float v = rs[mt][rh];
                v += __shfl_xor_sync(0xffffffffu, v, 1);
                v += __shfl_xor_sync(0xffffffffu, v, 2);
                if ((lane & 3) == 0)
                    red[(wm * 32 + mt * 16 + rh * 8 + (lane >> 2)) * 2 + wn] = v;
            }
        __syncthreads();
        if (tid < 128)
            atomicAdd(&g_ps_flat[cur_mblk * 128 + tid], red[tid * 2] + red[tid * 2 + 1]);
    }
}

// ---------------- combine ----------------
__global__ void __launch_bounds__(1024) combine_kernel(
    const int* __restrict__ captions, float* __restrict__ out)
{
    __shared__ float sh[1024];
    int tid = threadIdx.x;
    float local = 0.f;
    for (int r = tid; r < MROWS; r += 1024) {
        float S = g_ps_flat[r];
        int tg = captions[(r & 15) * 257 + (r >> 4) + 1];
        if (tg != 0) local += logf(S) - g_lt[r];
    }
    sh[tid] = local;
    __syncthreads();
    for (int o = 512; o > 0; o >>= 1) {
        if (tid < o) sh[tid] += sh[tid + o];
        __syncthreads();
    }
    if (tid == 0) out[0] = sh[0] * (1.f / NBATCH);
}

// ---------------- launch ----------------
extern "C" void kernel_launch(void* const* d_in, const int* in_sizes, int n_in,
                              void* d_out, int out_size) {
    const int*   captions = (const int*)d_in[0];
    const float* W_embed  = (const float*)d_in[1];
    const float* Wx       = (const float*)d_in[2];
    const float* Wh       = (const float*)d_in[3];
    const float* b        = (const float*)d_in[4];
    const float* W_vocab  = (const float*)d_in[5];
    const float* b_vocab  = (const float*)d_in[6];
    const float* h_init   = (const float*)d_in[7];

    cudaFuncSetAttribute(lstm_kernel,      cudaFuncAttributeMaxDynamicSharedMemorySize, L_SMEM);
    cudaFuncSetAttribute(vocab_kernel,     cudaFuncAttributeMaxDynamicSharedMemorySize, V_SMEM);
    cudaFuncSetAttribute(embed_mma_kernel, cudaFuncAttributeMaxDynamicSharedMemorySize, E_SMEM);

    init_kernel<<<32, 256>>>(h_init, b_vocab);
    prep_kernel<<<768, 256>>>(captions, W_embed, Wx);
    embed_mma_kernel<<<512, 256, E_SMEM>>>(b);
    lstm_kernel<<<32, 256, L_SMEM>>>(Wh);                      // 4th launch -> profiled
    conv_wv_kernel<<<dim3(VOCABSZ / 32, HIDDEN / 32), 256>>>(W_vocab);
    tgt_kernel<<<512, 256>>>(captions, b_vocab);
    vocab_kernel<<<VCTAS, 256, V_SMEM>>>();
    combine_kernel<<<1, 1024>>>(captions, (float*)d_out);
}

// round 15
// speedup vs baseline: 2.3542x; 1.0965x over previous
#include <cuda_runtime.h>
#include <cuda_bf16.h>
#include <cstdint>
#include <math.h>

#define VOCABSZ 32000
#define VPAD    32128
#define WORDVEC 256
#define HIDDEN  512
#define TSTEPS  256
#define NBATCH  16
#define G4      2048
#define MROWS   4096
#define NTILN   251          // VPAD / 128
#define NJOBS   (32 * NTILN) // 8032
#define VCTAS   148
#define LCTAS   64
#define LOG2E   1.44269504f

// ---------------- device scratch ----------------
__device__ float          g_xw[TSTEPS * NBATCH * G4];
__device__ __nv_bfloat16  g_hb[MROWS * HIDDEN];            // bf16 h history (written by lstm)
__device__ __nv_bfloat16  g_wvb[(size_t)VPAD * HIDDEN];    // Wv^T bf16 [v][k]
__device__ __nv_bfloat16  g_xb[MROWS * WORDVEC];           // gathered embeddings bf16
__device__ __nv_bfloat16  g_wxT[G4 * WORDVEC];             // Wx^T bf16
__device__ float          g_bv2[VPAD];                     // bv * LOG2E (pad = -120)
__device__ uint32_t       g_hpk2[2][NBATCH * HIDDEN];      // packed (hi,lo) bf16 h state
__device__ unsigned       g_barc[TSTEPS];
__device__ float          g_ps_flat[MROWS];                // per-row exp-sums (atomic)
__device__ float          g_lt[MROWS];

// ---------------- helpers ----------------
__device__ __forceinline__ float sigf(float x) { return __fdividef(1.f, 1.f + __expf(-x)); }
__device__ __forceinline__ float tanhf_fast(float x) { return __fdividef(2.f, 1.f + __expf(-2.f * x)) - 1.f; }
__device__ __forceinline__ uint32_t smem_to_u32(const void* p) {
    uint32_t a;
    asm("{ .reg .u64 t; cvta.to.shared.u64 t, %1; cvt.u32.u64 %0, t; }" : "=r"(a) : "l"(p));
    return a;
}
__device__ __forceinline__ float bf16lo_f(uint32_t u) { return __uint_as_float(u << 16); }
__device__ __forceinline__ float bf16hi_f(uint32_t u) { return __uint_as_float(u & 0xffff0000u); }
#define LDSM_X4(r, addr) asm volatile( \
    "ldmatrix.sync.aligned.m8n8.x4.shared.b16 {%0,%1,%2,%3}, [%4];" \
    : "=r"((r)[0]), "=r"((r)[1]), "=r"((r)[2]), "=r"((r)[3]) : "r"(addr))
#define LDSM_X2(r, addr) asm volatile( \
    "ldmatrix.sync.aligned.m8n8.x2.shared.b16 {%0,%1}, [%2];" \
    : "=r"((r)[0]), "=r"((r)[1]) : "r"(addr))
#define MMA16816(d, a, b0, b1) asm volatile( \
    "mma.sync.aligned.m16n8k16.row.col.f32.bf16.bf16.f32 " \
    "{%0,%1,%2,%3}, {%4,%5,%6,%7}, {%8,%9}, {%0,%1,%2,%3};" \
    : "+f"((d)[0]), "+f"((d)[1]), "+f"((d)[2]), "+f"((d)[3]) \
    : "r"((a)[0]), "r"((a)[1]), "r"((a)[2]), "r"((a)[3]), "r"(b0), "r"(b1))

__device__ __forceinline__ float exp2_fast(float t) {
    int i = __float2int_rn(t);
    float f = t - (float)i;
    float p = fmaf(f, 0.00133335581f, 0.00961812911f);
    p = fmaf(f, p, 0.0555041087f);
    p = fmaf(f, p, 0.240226507f);
    p = fmaf(f, p, 0.693147181f);
    p = fmaf(f, p, 1.0f);
    return __int_as_float(__float_as_int(p) + (i << 23));
}

__device__ __forceinline__ void grid_barrier(int idx, unsigned nblocks) {
    __threadfence();
    __syncthreads();
    if (threadIdx.x == 0) {
        atomicAdd(&g_barc[idx], 1u);
        volatile unsigned* p = &g_barc[idx];
        while (*p < nblocks) { }
        __threadfence();
    }
    __syncthreads();
}

// ---------------- init (every replay) ----------------
__global__ void __launch_bounds__(256) init_kernel(
    const float* __restrict__ h_init, const float* __restrict__ bv)
{
    int gid = blockIdx.x * 256 + threadIdx.x;            // 8192 threads
    if (gid < TSTEPS) g_barc[gid] = 0u;
    if (gid < MROWS) g_ps_flat[gid] = 0.f;
    if (gid < NBATCH * HIDDEN) {
        int k = gid & 511;
        float v = h_init[k];
        __nv_bfloat16 hi = __float2bfloat16(v);
        float hif = __bfloat162float(hi);
        __nv_bfloat16 lo = __float2bfloat16(v - hif);
        g_hpk2[0][gid] = ((uint32_t)*(uint16_t*)&hi << 16) | *(uint16_t*)&lo;
    }
    for (int j = gid; j < (VPAD - VOCABSZ) * HIDDEN; j += 8192)
        g_wvb[(size_t)VOCABSZ * HIDDEN + j] = __float2bfloat16(0.f);
    for (int j = gid; j < VPAD; j += 8192)
        g_bv2[j] = (j < VOCABSZ) ? bv[j] * LOG2E : -120.f;
}

// ---------------- prep: gather embeddings + Wx transpose (fused) ----------------
__global__ void __launch_bounds__(256) prep_kernel(
    const int* __restrict__ captions, const float* __restrict__ W_embed,
    const float* __restrict__ Wx)
{
    __shared__ float sh[32 * 33];
    if (blockIdx.x < 256) {
        int gid = blockIdx.x * 256 + threadIdx.x;
        int idx = gid * 4;
        int r = idx >> 8, d = idx & 255;
        int tok = captions[(r & 15) * 257 + (r >> 4)];
        float4 v = *(const float4*)&W_embed[tok * WORDVEC + d];
        __nv_bfloat16 o[4];
        o[0] = __float2bfloat16(v.x); o[1] = __float2bfloat16(v.y);
        o[2] = __float2bfloat16(v.z); o[3] = __float2bfloat16(v.w);
        *(uint2*)&g_xb[idx] = *(const uint2*)o;
    } else {
        int bid2 = blockIdx.x - 256;
        int n0 = (bid2 & 63) * 32, k0 = (bid2 >> 6) * 32;
        int tx = threadIdx.x & 31, ty = threadIdx.x >> 5;
        #pragma unroll
        for (int i = 0; i < 4; ++i) {
            int k = ty + i * 8;
            sh[k * 33 + tx] = Wx[(k0 + k) * G4 + n0 + tx];
        }
        __syncthreads();
        #pragma unroll
        for (int i = 0; i < 4; ++i) {
            int n = ty + i * 8;
            g_wxT[(n0 + n) * WORDVEC + k0 + tx] = __float2bfloat16(sh[tx * 33 + n]);
        }
    }
}

// ---------------- Wv transpose + bf16 ----------------
__global__ void __launch_bounds__(256) conv_wv_kernel(const float* __restrict__ Wv) {
    __shared__ float sh[32 * 33];
    int n0 = blockIdx.x * 32, k0 = blockIdx.y * 32;
    int tx = threadIdx.x & 31, ty = threadIdx.x >> 5;
    #pragma unroll
    for (int i = 0; i < 4; ++i) {
        int k = ty + i * 8;
        sh[k * 33 + tx] = Wv[(size_t)(k0 + k) * VOCABSZ + n0 + tx];
    }
    __syncthreads();
    #pragma unroll
    for (int i = 0; i < 4; ++i) {
        int n = ty + i * 8;
        g_wvb[(size_t)(n0 + n) * HIDDEN + k0 + tx] = __float2bfloat16(sh[tx * 33 + n]);
    }
}

// ---------------- embed GEMM (bf16 mma.sync) ----------------
#define E_A_STRIDE 264
#define E_B_OFF    67584
#define E_SMEM     135168
extern __shared__ __align__(16) char dsm_e[];
__global__ void __launch_bounds__(256, 1) embed_mma_kernel(const float* __restrict__ b) {
    __nv_bfloat16* As = (__nv_bfloat16*)dsm_e;
    __nv_bfloat16* Bs = (__nv_bfloat16*)(dsm_e + E_B_OFF);
    const int tid = threadIdx.x, lane = tid & 31, wid = tid >> 5;
    const int wm = wid >> 1, wn = wid & 1;
    const int mblk = blockIdx.x >> 4, nblk = blockIdx.x & 15;

    const uint4* asrc = (const uint4*)(g_xb + mblk * 128 * WORDVEC);
    const uint4* bsrc = (const uint4*)(g_wxT + nblk * 128 * WORDVEC);
    #pragma unroll
    for (int q = 0; q < 16; ++q) {
        int i = q * 256 + tid;
        int r = i >> 5, u = i & 31;
        *(uint4*)(As + r * E_A_STRIDE + u * 8) = asrc[i];
        *(uint4*)(Bs + r * E_A_STRIDE + u * 8) = bsrc[i];
    }
    __syncthreads();

    const uint32_t a_base = smem_to_u32(As);
    const uint32_t a_lane = (uint32_t)((lane & 15) * E_A_STRIDE + (lane >> 4) * 8) * 2;
    const int bq = lane >> 3;
    const uint32_t b_lane = (uint32_t)(((bq >> 1) * 8 + (lane & 7)) * E_A_STRIDE + (bq & 1) * 8) * 2;
    const uint32_t b_base = smem_to_u32(Bs) + (uint32_t)(wn * 64 * E_A_STRIDE) * 2;

    float d[2][8][4];
    #pragma unroll
    for (int mt = 0; mt < 2; ++mt)
        #pragma unroll
        for (int nt = 0; nt < 8; ++nt)
            #pragma unroll
            for (int e = 0; e < 4; ++e) d[mt][nt][e] = 0.f;

    #pragma unroll
    for (int k16 = 0; k16 < 16; ++k16) {
        const uint32_t koff = (uint32_t)(k16 * 16) * 2;
        uint32_t a[2][4];
        #pragma unroll
        for (int mt = 0; mt < 2; ++mt) {
            LDSM_X4(a[mt], a_base + a_lane + (uint32_t)((wm * 32 + mt * 16) * E_A_STRIDE) * 2 + koff);
        }
        #pragma unroll
        for (int np = 0; np < 4; ++np) {
            uint32_t bb[4];
            LDSM_X4(bb, b_base + b_lane + (uint32_t)(np * 16 * E_A_STRIDE) * 2 + koff);
            MMA16816(d[0][np * 2 + 0], a[0], bb[0], bb[1]);
            MMA16816(d[0][np * 2 + 1], a[0], bb[2], bb[3]);
            MMA16816(d[1][np * 2 + 0], a[1], bb[0], bb[1]);
            MMA16816(d[1][np * 2 + 1], a[1], bb[2], bb[3]);
        }
    }

    const int cbase = nblk * 128 + wn * 64 + (lane & 3) * 2;
    #pragma unroll
    for (int mt = 0; mt < 2; ++mt)
        #pragma unroll
        for (int rh = 0; rh < 2; ++rh) {
            int row = mblk * 128 + wm * 32 + mt * 16 + rh * 8 + (lane >> 2);
            #pragma unroll
            for (int nt = 0; nt < 8; ++nt) {
                int c = cbase + nt * 8;
                float2 v;
                v.x = d[mt][nt][rh * 2 + 0] + b[c];
                v.y = d[mt][nt][rh * 2 + 1] + b[c + 1];
                *(float2*)&g_xw[(size_t)row * G4 + c] = v;
            }
        }
}

// ---------------- persistent LSTM v4: 64 blocks, warp = (n8 rows) x (K-half) ----------
// Block owns 8 hidden units (32 gate-cols: row r = g*8+q, jcol = g*512 + bid*8 + q).
// 8 warps: rows (w&3)*8..+7, K-half (w>>2)*256. a_sh[2][32][17] partials, gates sum.
#define L_BH   0
#define L_BL   33280
#define L_AH   66560
#define L_AL   83200
#define L_ASH  99840
#define L_CSH  104192
#define L_SMEM 104704
extern __shared__ __align__(16) char dsm_l[];
__global__ void __launch_bounds__(256, 1) lstm_kernel(const float* __restrict__ Wh) {
    const int bid = blockIdx.x, tid = threadIdx.x;
    const int lane = tid & 31, wid = tid >> 5;
    uint16_t* Bh = (uint16_t*)(dsm_l + L_BH);    // [32][520]
    uint16_t* Bl = (uint16_t*)(dsm_l + L_BL);
    uint16_t* Ah = (uint16_t*)(dsm_l + L_AH);    // [16][520]
    uint16_t* Al = (uint16_t*)(dsm_l + L_AL);
    float* a_sh = (float*)(dsm_l + L_ASH);       // [2][32][17]
    float* c_sh = (float*)(dsm_l + L_CSH);       // [128]

    // one-time: Wh slice hi/lo (rows r=g*8+q, k)
    for (int i = tid; i < 32 * 512; i += 256) {
        int k = i >> 5, r = i & 31;
        int jcol = (r >> 3) * 512 + bid * 8 + (r & 7);
        float w = Wh[k * G4 + jcol];
        __nv_bfloat16 hi = __float2bfloat16(w);
        float hif = __bfloat162float(hi);
        __nv_bfloat16 lo = __float2bfloat16(w - hif);
        Bh[r * 520 + k] = *(uint16_t*)&hi;
        Bl[r * 520 + k] = *(uint16_t*)&lo;
    }
    if (tid < 128) c_sh[tid] = 0.f;

    const int q = tid & 7, n = tid >> 3;         // gate threads (tid<128)
    const int jglob = bid * 8 + q;

    const int nrow0 = (wid & 3) * 8;             // warp's 8 output rows
    const int kh = wid >> 2;                     // warp's K-half
    const uint32_t a_base_h = smem_to_u32(dsm_l + L_AH);
    const uint32_t a_base_l = smem_to_u32(dsm_l + L_AL);
    const uint32_t a_lane = (uint32_t)((lane & 15) * 520 + (lane >> 4) * 8) * 2;
    const uint32_t b_lane = (uint32_t)((nrow0 + (lane & 7)) * 520 + ((lane >> 3) & 1) * 8) * 2;
    const uint32_t b_base_h = smem_to_u32(dsm_l + L_BH) + b_lane;
    const uint32_t b_base_l = smem_to_u32(dsm_l + L_BL) + b_lane;
    const uint32_t khoff = (uint32_t)(kh * 256) * 2;

    for (int t = 0; t < TSTEPS; ++t) {
        // A fill: vectorized unpack of packed (hi,lo) h into two bf16 tiles [16][520]
        const uint4* src4 = (const uint4*)g_hpk2[t & 1];
        #pragma unroll
        for (int j = 0; j < 8; ++j) {
            int i4 = tid + j * 256;
            int an = i4 >> 7;
            int ak = (i4 << 2) & 511;
            uint4 u = __ldcg(&src4[i4]);
            uint32_t* ah32 = (uint32_t*)(Ah + an * 520 + ak);
            uint32_t* al32 = (uint32_t*)(Al + an * 520 + ak);
            ah32[0] = (u.y & 0xffff0000u) | (u.x >> 16);
            ah32[1] = (u.w & 0xffff0000u) | (u.z >> 16);
            al32[0] = (u.y << 16) | (u.x & 0xffffu);
            al32[1] = (u.w << 16) | (u.z & 0xffffu);
        }
        float xwv[4];
        if (tid < 128) {
            #pragma unroll
            for (int g = 0; g < 4; ++g)
                xwv[g] = g_xw[(size_t)(t * NBATCH + n) * G4 + g * 512 + jglob];
        }
        __syncthreads();

        // MMA: warp computes m16 x n8 over its K-half; 3 hi/lo terms
        {
            float dhh[4], dhl[4], dlh[4];
            #pragma unroll
            for (int e = 0; e < 4; ++e) { dhh[e] = 0.f; dhl[e] = 0.f; dlh[e] = 0.f; }

            #pragma unroll
            for (int s = 0; s < 16; ++s) {
                uint32_t koff = khoff + (uint32_t)(s * 16) * 2;
                uint32_t ah[4], al[4], bh[2], bl[2];
                LDSM_X4(ah, a_base_h + a_lane + koff);
                LDSM_X4(al, a_base_l + a_lane + koff);
                LDSM_X2(bh, b_base_h + koff);
                LDSM_X2(bl, b_base_l + koff);
                MMA16816(dhh, ah, bh[0], bh[1]);
                MMA16816(dhl, ah, bl[0], bl[1]);
                MMA16816(dlh, al, bh[0], bh[1]);
            }
            int m0 = lane >> 2, cc = 2 * (lane & 3);
            float e0 = dhh[0] + dhl[0] + dlh[0];
            float e1 = dhh[1] + dhl[1] + dlh[1];
            float e2 = dhh[2] + dhl[2] + dlh[2];
            float e3 = dhh[3] + dhl[3] + dlh[3];
            float* as = a_sh + kh * 32 * 17;
            as[(nrow0 + cc + 0) * 17 + m0]     = e0;
            as[(nrow0 + cc + 1) * 17 + m0]     = e1;
            as[(nrow0 + cc + 0) * 17 + m0 + 8] = e2;
            as[(nrow0 + cc + 1) * 17 + m0 + 8] = e3;
        }
        __syncthreads();

        // gates: tid<128, (n, q)
        if (tid < 128) {
            float av0 = a_sh[( 0 + q) * 17 + n] + a_sh[(32 * 17) + ( 0 + q) * 17 + n] + xwv[0];
            float av1 = a_sh[( 8 + q) * 17 + n] + a_sh[(32 * 17) + ( 8 + q) * 17 + n] + xwv[1];
            float av2 = a_sh[(16 + q) * 17 + n] + a_sh[(32 * 17) + (16 + q) * 17 + n] + xwv[2];
            float av3 = a_sh[(24 + q) * 17 + n] + a_sh[(32 * 17) + (24 + q) * 17 + n] + xwv[3];
            float ig = sigf(av0), fg = sigf(av1), og = sigf(av2), gg = tanhf_fast(av3);
            float c  = fg * c_sh[tid] + ig * gg;
            float hh = og * tanhf_fast(c);
            c_sh[tid] = c;
            __nv_bfloat16 hi = __float2bfloat16(hh);
            float hif = __bfloat162float(hi);
            __nv_bfloat16 lo = __float2bfloat16(hh - hif);
            g_hpk2[(t & 1) ^ 1][n * HIDDEN + jglob] =
                ((uint32_t)*(uint16_t*)&hi << 16) | *(uint16_t*)&lo;
            g_hb[t * (NBATCH * HIDDEN) + n * HIDDEN + jglob] = hi;
        }
        grid_barrier(t, LCTAS);
    }
}

// ---------------- target logits (bf16 h, consistent with vocab GEMM) ----------------
__global__ void __launch_bounds__(256) tgt_kernel(
    const int* __restrict__ captions, const float* __restrict__ bv)
{
    int wid = threadIdx.x >> 5, lane = threadIdx.x & 31;
    int r = blockIdx.x * 8 + wid;
    int tg = captions[(r & 15) * 257 + (r >> 4) + 1];
    const uint4* hp4 = (const uint4*)(g_hb + (size_t)r * HIDDEN);
    const uint4* wp4 = (const uint4*)(g_wvb + (size_t)tg * HIDDEN);
    float s = 0.f;
    #pragma unroll
    for (int i = 0; i < 2; ++i) {
        uint4 hu = hp4[lane + i * 32];
        uint4 wu = wp4[lane + i * 32];
        s = fmaf(bf16lo_f(hu.x), bf16lo_f(wu.x), s);
        s = fmaf(bf16hi_f(hu.x), bf16hi_f(wu.x), s);
        s = fmaf(bf16lo_f(hu.y), bf16lo_f(wu.y), s);
        s = fmaf(bf16hi_f(hu.y), bf16hi_f(wu.y), s);
        s = fmaf(bf16lo_f(hu.z), bf16lo_f(wu.z), s);
        s = fmaf(bf16hi_f(hu.z), bf16hi_f(wu.z), s);
        s = fmaf(bf16lo_f(hu.w), bf16lo_f(wu.w), s);
        s = fmaf(bf16hi_f(hu.w), bf16hi_f(wu.w), s);
    }
    #pragma unroll
    for (int o = 16; o > 0; o >>= 1) s += __shfl_xor_sync(0xffffffffu, s, o);
    if (lane == 0) g_lt[r] = s + bv[tg];
}

// ---------------- vocab v3: flat jobs over 148 CTAs, bf16 mma + streaming exp-sum -----
#define V_A_STRIDE 520
#define V_B_OFF    133120
#define V_B_SZ     18432
#define V_B_STRIDE 72
#define V_RED_OFF  169984
#define V_SMEM     171008
extern __shared__ __align__(16) char dsm_v[];
__global__ void __launch_bounds__(256, 1) vocab_kernel() {
    __nv_bfloat16* As = (__nv_bfloat16*)dsm_v;
    float* red = (float*)(dsm_v + V_RED_OFF);
    const int tid = threadIdx.x, lane = tid & 31, wid = tid >> 5;
    const int wm = wid >> 1, wn = wid & 1;

    const int start = (int)(((long long)blockIdx.x * NJOBS) / VCTAS);
    const int end   = (int)(((long long)(blockIdx.x + 1) * NJOBS) / VCTAS);

    const uint32_t a_base = smem_to_u32(dsm_v);
    const uint32_t a_lane = (uint32_t)((lane & 15) * V_A_STRIDE + (lane >> 4) * 8) * 2;
    const int bq = lane >> 3;
    const uint32_t b_lane = (uint32_t)(((bq >> 1) * 8 + (lane & 7)) * V_B_STRIDE + (bq & 1) * 8) * 2;

    float rs[2][2] = {{0.f, 0.f}, {0.f, 0.f}};
    int cur_mblk = -1;

    for (int j = start; j < end; ++j) {
        const int mblk = j / NTILN, nt = j % NTILN;

        if (mblk != cur_mblk) {
            if (cur_mblk >= 0) {
                #pragma unroll
                for (int mt = 0; mt < 2; ++mt)
                    #pragma unroll
                    for (int rh = 0; rh < 2; ++rh) {
                        float v = rs[mt][rh];
                        v += __shfl_xor_sync(0xffffffffu, v, 1);
                        v += __shfl_xor_sync(0xffffffffu, v, 2);
                        if ((lane & 3) == 0)
                            red[(wm * 32 + mt * 16 + rh * 8 + (lane >> 2)) * 2 + wn] = v;
                        rs[mt][rh] = 0.f;
                    }
                __syncthreads();
                if (tid < 128)
                    atomicAdd(&g_ps_flat[cur_mblk * 128 + tid], red[tid * 2] + red[tid * 2 + 1]);
            }
            __syncthreads();
            const uint4* src = (const uint4*)(g_hb + (size_t)(mblk * 128) * HIDDEN);
            for (int i = tid; i < 8192; i += 256) {
                int r = i >> 6, u = i & 63;
                *(uint4*)(As + r * V_A_STRIDE + u * 8) = src[i];
            }
            __syncthreads();
            cur_mblk = mblk;
        }

        const int nbase = nt * 128;
        float bb[16];
        {
            int cb = nbase + wn * 64 + (lane & 3) * 2;
            #pragma unroll
            for (int nt2 = 0; nt2 < 8; ++nt2) {
                bb[nt2 * 2 + 0] = g_bv2[cb + nt2 * 8 + 0];
                bb[nt2 * 2 + 1] = g_bv2[cb + nt2 * 8 + 1];
            }
        }
        float d[2][8][4];
        #pragma unroll
        for (int mt = 0; mt < 2; ++mt)
            #pragma unroll
            for (int nt2 = 0; nt2 < 8; ++nt2)
                #pragma unroll
                for (int e = 0; e < 4; ++e) d[mt][nt2][e] = 0.f;

        uint4 ld[4];
        #pragma unroll
        for (int qq = 0; qq < 4; ++qq) {
            int i = qq * 256 + tid;
            int n = i >> 3, u = i & 7;
            ld[qq] = *(const uint4*)(g_wvb + (size_t)(nbase + n) * HIDDEN + u * 8);
        }
        #pragma unroll
        for (int qq = 0; qq < 4; ++qq) {
            int i = qq * 256 + tid;
            int n = i >> 3, u = i & 7;
            *(uint4*)((__nv_bfloat16*)(dsm_v + V_B_OFF) + n * V_B_STRIDE + u * 8) = ld[qq];
        }
        __syncthreads();

        for (int kc = 0; kc < 8; ++kc) {
            if (kc < 7) {
                #pragma unroll
                for (int qq = 0; qq < 4; ++qq) {
                    int i = qq * 256 + tid;
                    int n = i >> 3, u = i & 7;
                    ld[qq] = *(const uint4*)(g_wvb + (size_t)(nbase + n) * HIDDEN + (kc + 1) * 64 + u * 8);
                }
            }
            const uint32_t b_base = smem_to_u32(dsm_v + V_B_OFF + (kc & 1) * V_B_SZ) + (uint32_t)(wn * 64 * V_B_STRIDE) * 2;
            #pragma unroll
            for (int k16 = 0; k16 < 4; ++k16) {
                uint32_t a[2][4];
                #pragma unroll
                for (int mt = 0; mt < 2; ++mt) {
                    uint32_t aaddr = a_base + a_lane +
                        (uint32_t)((wm * 32 + mt * 16) * V_A_STRIDE + kc * 64 + k16 * 16) * 2;
                    LDSM_X4(a[mt], aaddr);
                }
                #pragma unroll
                for (int np = 0; np < 4; ++np) {
                    uint32_t b[4];
                    uint32_t baddr = b_base + b_lane + (uint32_t)(np * 16 * V_B_STRIDE + k16 * 16) * 2;
                    LDSM_X4(b, baddr);
                    MMA16816(d[0][np * 2 + 0], a[0], b[0], b[1]);
                    MMA16816(d[0][np * 2 + 1], a[0], b[2], b[3]);
                    MMA16816(d[1][np * 2 + 0], a[1], b[0], b[1]);
                    MMA16816(d[1][np * 2 + 1], a[1], b[2], b[3]);
                }
            }
            if (kc < 7) {
                __nv_bfloat16* dst = (__nv_bfloat16*)(dsm_v + V_B_OFF + ((kc + 1) & 1) * V_B_SZ);
                #pragma unroll
                for (int qq = 0; qq < 4; ++qq) {
                    int i = qq * 256 + tid;
                    int n = i >> 3, u = i & 7;
                    *(uint4*)(dst + n * V_B_STRIDE + u * 8) = ld[qq];
                }
            }
            __syncthreads();
        }

        #pragma unroll
        for (int mt = 0; mt < 2; ++mt)
            #pragma unroll
            for (int rh = 0; rh < 2; ++rh) {
                float s = 0.f;
                #pragma unroll
                for (int nt2 = 0; nt2 < 8; ++nt2) {
                    s += exp2_fast(fmaf(d[mt][nt2][rh * 2 + 0], LOG2E, bb[nt2 * 2 + 0]));
                    s += exp2_fast(fmaf(d[mt][nt2][rh * 2 + 1], LOG2E, bb[nt2 * 2 + 1]));
                }
                rs[mt][rh] += s;
            }
    }

    if (cur_mblk >= 0) {
        #pragma unroll
        for (int mt = 0; mt < 2; ++mt)
            #pragma unroll
            for (int rh = 0; rh < 2; ++rh) {
                float v = rs[mt][rh];
                v += __shfl_xor_sync(0xffffffffu, v, 1);
                v += __shfl_xor_sync(0xffffffffu, v, 2);
                if ((lane & 3) == 0)
                    red[(wm * 32 + mt * 16 + rh * 8 + (lane >> 2)) * 2 + wn] = v;
            }
        __syncthreads();
        if (tid < 128)
            atomicAdd(&g_ps_flat[cur_mblk * 128 + tid], red[tid * 2] + red[tid * 2 + 1]);
    }
}

// ---------------- combine ----------------
__global__ void __launch_bounds__(1024) combine_kernel(
    const int* __restrict__ captions, float* __restrict__ out)
{
    __shared__ float sh[1024];
    int tid = threadIdx.x;
    float local = 0.f;
    for (int r = tid; r < MROWS; r += 1024) {
        float S = g_ps_flat[r];
        int tg = captions[(r & 15) * 257 + (r >> 4) + 1];
        if (tg != 0) local += logf(S) - g_lt[r];
    }
    sh[tid] = local;
    __syncthreads();
    for (int o = 512; o > 0; o >>= 1) {
        if (tid < o) sh[tid] += sh[tid + o];
        __syncthreads();
    }
    if (tid == 0) out[0] = sh[0] * (1.f / NBATCH);
}

// ---------------- launch ----------------
extern "C" void kernel_launch(void* const* d_in, const int* in_sizes, int n_in,
                              void* d_out, int out_size) {
    const int*   captions = (const int*)d_in[0];
    const float* W_embed  = (const float*)d_in[1];
    const float* Wx       = (const float*)d_in[2];
    const float* Wh       = (const float*)d_in[3];
    const float* b        = (const float*)d_in[4];
    const float* W_vocab  = (const float*)d_in[5];
    const float* b_vocab  = (const float*)d_in[6];
    const float* h_init   = (const float*)d_in[7];

    cudaFuncSetAttribute(lstm_kernel,      cudaFuncAttributeMaxDynamicSharedMemorySize, L_SMEM);
    cudaFuncSetAttribute(vocab_kernel,     cudaFuncAttributeMaxDynamicSharedMemorySize, V_SMEM);
    cudaFuncSetAttribute(embed_mma_kernel, cudaFuncAttributeMaxDynamicSharedMemorySize, E_SMEM);

    init_kernel<<<32, 256>>>(h_init, b_vocab);
    prep_kernel<<<768, 256>>>(captions, W_embed, Wx);
    embed_mma_kernel<<<512, 256, E_SMEM>>>(b);
    lstm_kernel<<<LCTAS, 256, L_SMEM>>>(Wh);                   // 4th launch -> profiled
    conv_wv_kernel<<<dim3(VOCABSZ / 32, HIDDEN / 32), 256>>>(W_vocab);
    tgt_kernel<<<512, 256>>>(captions, b_vocab);
    vocab_kernel<<<VCTAS, 256, V_SMEM>>>();
    combine_kernel<<<1, 1024>>>(captions, (float*)d_out);
}